// round 4
// baseline (speedup 1.0000x reference)
#include <cuda_runtime.h>
#include <cuda_bf16.h>
#include <math.h>

// Problem constants
#define BATCH 8
#define HGT 32
#define WID 32
#define DIM 768
#define NH 12
#define HD 64
#define LSEQ 1024            // HGT*WID
#define MROWS (BATCH*LSEQ)   // 8192
#define NQKV (3*DIM)         // 2304

// ---------------- scratch (static device globals; no allocation) ----------------
__device__ float g_qkv[MROWS * NQKV];          // (B,L,3*dim)
__device__ float g_q[BATCH * NH * LSEQ * HD];  // (B,nH,L,hd) rope'd
__device__ float g_k[BATCH * NH * LSEQ * HD];
__device__ float g_v[BATCH * NH * LSEQ * HD];
__device__ float g_att[MROWS * DIM];           // (B,L,dim) attention output

// ---------------- tiled NT GEMM: C[m,n] = sum_k A[m,k]*B[n,k] + bias[n] ----------
// A: (M,K) row-major, B: (N,K) row-major. M,N multiples of 64, K multiple of 32.
#define GBM 64
#define GBN 64
#define GBK 32

__global__ __launch_bounds__(256) void gemm_nt_bias(
    const float* __restrict__ A, const float* __restrict__ Bm,
    const float* __restrict__ bias, float* __restrict__ C,
    int Mdim, int Ndim, int Kdim)
{
    __shared__ float As[GBK][GBM + 4];  // row stride 68 -> float4-aligned, few conflicts
    __shared__ float Bs[GBK][GBN + 4];

    const int tid = threadIdx.x;
    const int tx = tid & 15;        // 0..15 -> n micro
    const int ty = tid >> 4;        // 0..15 -> m micro
    const int m0 = blockIdx.y * GBM;
    const int n0 = blockIdx.x * GBN;

    float acc[4][4];
#pragma unroll
    for (int i = 0; i < 4; i++)
#pragma unroll
        for (int j = 0; j < 4; j++) acc[i][j] = 0.f;

    const int lr = tid >> 3;          // 0..31 rows
    const int lc = (tid & 7) * 4;     // 0..28 cols (k)

    for (int k0 = 0; k0 < Kdim; k0 += GBK) {
        float4 a0 = *(const float4*)&A[(size_t)(m0 + lr) * Kdim + k0 + lc];
        float4 a1 = *(const float4*)&A[(size_t)(m0 + lr + 32) * Kdim + k0 + lc];
        float4 b0 = *(const float4*)&Bm[(size_t)(n0 + lr) * Kdim + k0 + lc];
        float4 b1 = *(const float4*)&Bm[(size_t)(n0 + lr + 32) * Kdim + k0 + lc];

        __syncthreads();
        As[lc + 0][lr] = a0.x; As[lc + 1][lr] = a0.y; As[lc + 2][lr] = a0.z; As[lc + 3][lr] = a0.w;
        As[lc + 0][lr + 32] = a1.x; As[lc + 1][lr + 32] = a1.y; As[lc + 2][lr + 32] = a1.z; As[lc + 3][lr + 32] = a1.w;
        Bs[lc + 0][lr] = b0.x; Bs[lc + 1][lr] = b0.y; Bs[lc + 2][lr] = b0.z; Bs[lc + 3][lr] = b0.w;
        Bs[lc + 0][lr + 32] = b1.x; Bs[lc + 1][lr + 32] = b1.y; Bs[lc + 2][lr + 32] = b1.z; Bs[lc + 3][lr + 32] = b1.w;
        __syncthreads();

#pragma unroll
        for (int kk = 0; kk < GBK; kk++) {
            float4 av = *(const float4*)&As[kk][ty * 4];
            float4 bv = *(const float4*)&Bs[kk][tx * 4];
            float a[4] = {av.x, av.y, av.z, av.w};
            float b[4] = {bv.x, bv.y, bv.z, bv.w};
#pragma unroll
            for (int i = 0; i < 4; i++)
#pragma unroll
                for (int j = 0; j < 4; j++) acc[i][j] += a[i] * b[j];
        }
    }

    float4 bb = *(const float4*)&bias[n0 + tx * 4];
    float bj[4] = {bb.x, bb.y, bb.z, bb.w};
#pragma unroll
    for (int i = 0; i < 4; i++) {
        float4 o;
        o.x = acc[i][0] + bj[0];
        o.y = acc[i][1] + bj[1];
        o.z = acc[i][2] + bj[2];
        o.w = acc[i][3] + bj[3];
        *(float4*)&C[(size_t)(m0 + ty * 4 + i) * Ndim + n0 + tx * 4] = o;
    }
}

// ---------------- split qkv + 2D axial RoPE ----------------
// one thread per (b,n,l, pair j in [0,32)); handles q,k (rope) and v (copy)
__global__ __launch_bounds__(256) void rope_split_kernel(
    const float* __restrict__ qkv,
    float* __restrict__ q, float* __restrict__ k, float* __restrict__ v)
{
    int idx = blockIdx.x * blockDim.x + threadIdx.x;
    const int TOT = BATCH * NH * LSEQ * (HD / 2);
    if (idx >= TOT) return;
    int j = idx & 31;
    int l = (idx >> 5) & (LSEQ - 1);
    int n = (idx >> 15) % NH;
    int b = idx / (32 * LSEQ * NH);

    size_t in_base = ((size_t)(b * LSEQ + l)) * NQKV + n * HD + 2 * j;
    size_t out_base = ((size_t)((b * NH + n) * LSEQ + l)) * HD + 2 * j;

    int i = j & 15;
    float pos = (j < 16) ? (float)(l & 31) : (float)(l >> 5);
    // f_i = 10000^(-i/16) ; log2(10000) = 13.287712379549449
    float f = exp2f(-(float)i * (13.287712379549449f / 16.0f));
    float ang = pos * f;
    float sn, cs;
    sincosf(ang, &sn, &cs);

    float2 qa = *(const float2*)&qkv[in_base];
    float2 ka = *(const float2*)&qkv[in_base + DIM];
    float2 va = *(const float2*)&qkv[in_base + 2 * DIM];

    float2 qo, ko;
    qo.x = qa.x * cs - qa.y * sn; qo.y = qa.x * sn + qa.y * cs;
    ko.x = ka.x * cs - ka.y * sn; ko.y = ka.x * sn + ka.y * cs;

    *(float2*)&q[out_base] = qo;
    *(float2*)&k[out_base] = ko;
    *(float2*)&v[out_base] = va;
}

// ---------------- attention ----------------
// block: 256 threads, one (b*nH) head slice x 16-query tile.
// smem: full score tile [16][1024] (stride 1032), q tile, rel biases.
#define TQ 16
#define SSTR 1032
#define QSTR 68
#define RSTR 33
#define ATTN_SMEM_FLOATS (TQ*SSTR + TQ*QSTR + 2*TQ*RSTR + TQ)
#define ATTN_SMEM_BYTES (ATTN_SMEM_FLOATS * 4)

__global__ __launch_bounds__(256) void attn_kernel(
    const float* __restrict__ Q, const float* __restrict__ K,
    const float* __restrict__ V, const float* __restrict__ rph,
    const float* __restrict__ rpw, float* __restrict__ Out)
{
    extern __shared__ float sm[];
    float* sc = sm;                           // TQ * SSTR
    float* qs = sc + TQ * SSTR;               // TQ * QSTR
    float* rh = qs + TQ * QSTR;               // TQ * RSTR
    float* rw = rh + TQ * RSTR;               // TQ * RSTR
    float* ssum = rw + TQ * RSTR;             // TQ

    const int tid = threadIdx.x;
    const int bn = blockIdx.y;                // b*NH + n
    const int b = bn / NH, n = bn % NH;
    const int q0 = blockIdx.x * TQ;

    const float* Qb = Q + ((size_t)bn * LSEQ + q0) * HD;
    const float* Kb = K + (size_t)bn * LSEQ * HD;
    const float* Vb = V + (size_t)bn * LSEQ * HD;

    // load 16x64 q tile (contiguous 1024 floats)
    {
        float4 t4 = ((const float4*)Qb)[tid];
        int qq = tid >> 4;
        int dd = (tid & 15) * 4;
        *(float4*)&qs[qq * QSTR + dd] = t4;
    }
    __syncthreads();

    // rel position biases: 16 queries x (32 h + 32 w) dots of length 64
    for (int u = tid; u < TQ * 64; u += 256) {
        int qq = u >> 6, j = u & 63;
        int lq = q0 + qq;
        int ridx;
        const float* rp;
        if (j < 32) { ridx = (lq >> 5) - j + (HGT - 1); rp = rph; }
        else        { ridx = (lq & 31) - (j - 32) + (WID - 1); rp = rpw; }
        const float* rr = rp + ridx * HD;
        float acc = 0.f;
#pragma unroll
        for (int d = 0; d < HD; d += 4) {
            float4 r4 = *(const float4*)&rr[d];
            float4 q4 = *(const float4*)&qs[qq * QSTR + d];
            acc += q4.x * r4.x + q4.y * r4.y + q4.z * r4.z + q4.w * r4.w;
        }
        if (j < 32) rh[qq * RSTR + j] = acc;
        else        rw[qq * RSTR + (j - 32)] = acc;
    }
    __syncthreads();

    // scores: thread = (q = tid&15, key offset = tid>>4); loop key tiles of 16
    {
        const int qq = tid & 15;
        const int dk = tid >> 4;
        const float rscale = 0.125f; // 1/sqrt(64)
        for (int k0 = 0; k0 < LSEQ; k0 += 16) {
            int kk = k0 + dk;
            const float* Kr = Kb + (size_t)kk * HD;
            float acc = 0.f;
#pragma unroll
            for (int d = 0; d < HD; d += 4) {
                float4 k4 = *(const float4*)&Kr[d];
                float4 q4 = *(const float4*)&qs[qq * QSTR + d];
                acc += q4.x * k4.x + q4.y * k4.y + q4.z * k4.z + q4.w * k4.w;
            }
            sc[qq * SSTR + kk] = acc * rscale + rh[qq * RSTR + (kk >> 5)] + rw[qq * RSTR + (kk & 31)];
        }
    }
    __syncthreads();

    // softmax per row (unnormalized exp; keep row sums)
    {
        const int wid = tid >> 5, lane = tid & 31;
        for (int r = wid; r < TQ; r += 8) {
            float m = -1e30f;
            for (int kk = lane; kk < LSEQ; kk += 32) m = fmaxf(m, sc[r * SSTR + kk]);
#pragma unroll
            for (int o = 16; o; o >>= 1) m = fmaxf(m, __shfl_xor_sync(0xffffffffu, m, o));
            float s = 0.f;
            for (int kk = lane; kk < LSEQ; kk += 32) {
                float e = expf(sc[r * SSTR + kk] - m);
                sc[r * SSTR + kk] = e;
                s += e;
            }
#pragma unroll
            for (int o = 16; o; o >>= 1) s += __shfl_xor_sync(0xffffffffu, s, o);
            if (lane == 0) ssum[r] = s;
        }
    }
    __syncthreads();

    // AV: thread = (d = tid&63, key-group g = tid>>6 covering 256 keys)
    {
        const int d = tid & 63;
        const int g = tid >> 6;
        float acc[TQ];
#pragma unroll
        for (int i = 0; i < TQ; i++) acc[i] = 0.f;
        const int kbeg = g * 256, kend = kbeg + 256;
        for (int kk = kbeg; kk < kend; kk++) {
            float vv = Vb[(size_t)kk * HD + d];
#pragma unroll
            for (int i = 0; i < TQ; i++) acc[i] += sc[i * SSTR + kk] * vv;
        }
        __syncthreads();
        // reduce 4 key-groups via smem (reuse score region)
        float* part = sm; // 4*16*64 = 4096 floats, fits inside sc region
#pragma unroll
        for (int i = 0; i < TQ; i++) part[(g * TQ + i) * HD + d] = acc[i];
        __syncthreads();
        for (int u = tid; u < TQ * HD; u += 256) {
            int qq = u >> 6, dd = u & 63;
            float s = part[(0 * TQ + qq) * HD + dd] + part[(1 * TQ + qq) * HD + dd]
                    + part[(2 * TQ + qq) * HD + dd] + part[(3 * TQ + qq) * HD + dd];
            s /= ssum[qq];
            int l = q0 + qq;
            Out[((size_t)b * LSEQ + l) * DIM + n * HD + dd] = s;
        }
    }
}

// ---------------- launch ----------------
extern "C" void kernel_launch(void* const* d_in, const int* in_sizes, int n_in,
                              void* d_out, int out_size)
{
    const float* x      = (const float*)d_in[0];
    const float* qkv_w  = (const float*)d_in[1];
    const float* qkv_b  = (const float*)d_in[2];
    const float* proj_w = (const float*)d_in[3];
    const float* proj_b = (const float*)d_in[4];
    const float* rph    = (const float*)d_in[5];
    const float* rpw    = (const float*)d_in[6];
    float* out = (float*)d_out;

    float *p_qkv, *p_q, *p_k, *p_v, *p_att;
    cudaGetSymbolAddress((void**)&p_qkv, g_qkv);
    cudaGetSymbolAddress((void**)&p_q, g_q);
    cudaGetSymbolAddress((void**)&p_k, g_k);
    cudaGetSymbolAddress((void**)&p_v, g_v);
    cudaGetSymbolAddress((void**)&p_att, g_att);

    // 1) QKV GEMM: (8192x768) @ (2304x768)^T + b
    gemm_nt_bias<<<dim3(NQKV / GBN, MROWS / GBM), 256>>>(
        x, qkv_w, qkv_b, p_qkv, MROWS, NQKV, DIM);

    // 2) split + rope
    {
        const int TOT = BATCH * NH * LSEQ * (HD / 2);
        rope_split_kernel<<<(TOT + 255) / 256, 256>>>(p_qkv, p_q, p_k, p_v);
    }

    // 3) attention
    cudaFuncSetAttribute(attn_kernel, cudaFuncAttributeMaxDynamicSharedMemorySize,
                         ATTN_SMEM_BYTES);
    attn_kernel<<<dim3(LSEQ / TQ, BATCH * NH), 256, ATTN_SMEM_BYTES>>>(
        p_q, p_k, p_v, rph, rpw, p_att);

    // 4) output projection: (8192x768) @ (768x768)^T + b
    gemm_nt_bias<<<dim3(DIM / GBN, MROWS / GBM), 256>>>(
        p_att, proj_w, proj_b, out, MROWS, DIM, DIM);
}

// round 5
// speedup vs baseline: 1.8750x; 1.8750x over previous
#include <cuda_runtime.h>
#include <math.h>

// Problem constants
#define BATCH 8
#define HGT 32
#define WID 32
#define DIM 768
#define NH 12
#define HD 64
#define LSEQ 1024
#define MROWS (BATCH*LSEQ)      // 8192
#define NQKV (3*DIM)            // 2304
#define NHEADS (BATCH*NH)       // 96

// ---------------- scratch (static device globals; no allocation) ----------------
__device__ float g_qkv[MROWS * NQKV];                 // (B,L,3*dim)      75 MB
__device__ float g_q[NHEADS * LSEQ * HD];             // roped q          25 MB
__device__ float g_k[NHEADS * LSEQ * HD];             // roped k          25 MB
__device__ float g_vt[NHEADS * HD * LSEQ];            // V transposed     25 MB
__device__ float g_att[MROWS * DIM];                  // attn output      25 MB
__device__ float g_P[NHEADS * LSEQ * LSEQ];           // probs           402 MB
__device__ float g_rh[NHEADS * LSEQ * 32];            // rel_h bias     12.6 MB
__device__ float g_rw[NHEADS * LSEQ * 32];            // rel_w bias     12.6 MB

// ================= generic NT GEMM: C[m,n] = sum_k A[m,k]*B[n,k] (+bias[n]) =====
// 128x128 block tile, BK=16, 256 threads, 8x8 micro-tile (split 4+4 at offsets 0/64)
__global__ __launch_bounds__(256) void gemm_nt_bias(
    const float* __restrict__ A, const float* __restrict__ Bm,
    const float* __restrict__ bias, float* __restrict__ C,
    int Ndim, int Kdim)
{
    __shared__ float As[16][132];
    __shared__ float Bs[16][132];
    const int tid = threadIdx.x;
    const int tx = tid & 15, ty = tid >> 4;
    const int m0 = blockIdx.y * 128, n0 = blockIdx.x * 128;
    const int lr = tid >> 2, lc = (tid & 3) * 4;

    float acc[8][8];
#pragma unroll
    for (int i = 0; i < 8; i++)
#pragma unroll
        for (int j = 0; j < 8; j++) acc[i][j] = 0.f;

    const float* Ar0 = A + (size_t)(m0 + lr) * Kdim + lc;
    const float* Ar1 = Ar0 + (size_t)64 * Kdim;
    const float* Br0 = Bm + (size_t)(n0 + lr) * Kdim + lc;
    const float* Br1 = Br0 + (size_t)64 * Kdim;

    for (int k0 = 0; k0 < Kdim; k0 += 16) {
        float4 a0 = *(const float4*)(Ar0 + k0);
        float4 a1 = *(const float4*)(Ar1 + k0);
        float4 b0 = *(const float4*)(Br0 + k0);
        float4 b1 = *(const float4*)(Br1 + k0);
        __syncthreads();
        As[lc+0][lr] = a0.x; As[lc+1][lr] = a0.y; As[lc+2][lr] = a0.z; As[lc+3][lr] = a0.w;
        As[lc+0][lr+64] = a1.x; As[lc+1][lr+64] = a1.y; As[lc+2][lr+64] = a1.z; As[lc+3][lr+64] = a1.w;
        Bs[lc+0][lr] = b0.x; Bs[lc+1][lr] = b0.y; Bs[lc+2][lr] = b0.z; Bs[lc+3][lr] = b0.w;
        Bs[lc+0][lr+64] = b1.x; Bs[lc+1][lr+64] = b1.y; Bs[lc+2][lr+64] = b1.z; Bs[lc+3][lr+64] = b1.w;
        __syncthreads();
#pragma unroll
        for (int kk = 0; kk < 16; kk++) {
            float4 xa = *(const float4*)&As[kk][ty * 4];
            float4 xb = *(const float4*)&As[kk][64 + ty * 4];
            float4 ya = *(const float4*)&Bs[kk][tx * 4];
            float4 yb = *(const float4*)&Bs[kk][64 + tx * 4];
            float am[8] = {xa.x, xa.y, xa.z, xa.w, xb.x, xb.y, xb.z, xb.w};
            float bv[8] = {ya.x, ya.y, ya.z, ya.w, yb.x, yb.y, yb.z, yb.w};
#pragma unroll
            for (int i = 0; i < 8; i++)
#pragma unroll
                for (int j = 0; j < 8; j++)
                    acc[i][j] = fmaf(am[i], bv[j], acc[i][j]);
        }
    }

    float4 bb0 = make_float4(0.f, 0.f, 0.f, 0.f), bb1 = bb0;
    if (bias) {
        bb0 = *(const float4*)&bias[n0 + tx * 4];
        bb1 = *(const float4*)&bias[n0 + 64 + tx * 4];
    }
#pragma unroll
    for (int i = 0; i < 8; i++) {
        int m = m0 + ((i < 4) ? (ty * 4 + i) : (64 + ty * 4 + i - 4));
        float4 o0 = make_float4(acc[i][0] + bb0.x, acc[i][1] + bb0.y,
                                acc[i][2] + bb0.z, acc[i][3] + bb0.w);
        float4 o1 = make_float4(acc[i][4] + bb1.x, acc[i][5] + bb1.y,
                                acc[i][6] + bb1.z, acc[i][7] + bb1.w);
        *(float4*)&C[(size_t)m * Ndim + n0 + tx * 4] = o0;
        *(float4*)&C[(size_t)m * Ndim + n0 + 64 + tx * 4] = o1;
    }
}

// ================= split qkv + 2D axial RoPE (q,k only) =========================
__global__ __launch_bounds__(256) void rope_split_kernel(
    const float* __restrict__ qkv, float* __restrict__ q, float* __restrict__ k)
{
    int idx = blockIdx.x * blockDim.x + threadIdx.x;
    const int TOT = NHEADS * LSEQ * (HD / 2);
    if (idx >= TOT) return;
    int j = idx & 31;
    int l = (idx >> 5) & (LSEQ - 1);
    int n = (idx >> 15) % NH;
    int b = idx / (32 * LSEQ * NH);

    size_t in_base = ((size_t)(b * LSEQ + l)) * NQKV + n * HD + 2 * j;
    size_t out_base = ((size_t)((b * NH + n) * LSEQ + l)) * HD + 2 * j;

    int i = j & 15;
    float pos = (j < 16) ? (float)(l & 31) : (float)(l >> 5);
    float f = exp2f(-(float)i * (13.287712379549449f / 16.0f));
    float sn, cs;
    sincosf(pos * f, &sn, &cs);

    float2 qa = *(const float2*)&qkv[in_base];
    float2 ka = *(const float2*)&qkv[in_base + DIM];
    float2 qo, ko;
    qo.x = qa.x * cs - qa.y * sn; qo.y = qa.x * sn + qa.y * cs;
    ko.x = ka.x * cs - ka.y * sn; ko.y = ka.x * sn + ka.y * cs;
    *(float2*)&q[out_base] = qo;
    *(float2*)&k[out_base] = ko;
}

// ================= V transpose: (bn, l, d) -> (bn, d, l) ========================
__global__ __launch_bounds__(256) void vtrans_kernel(
    const float* __restrict__ qkv, float* __restrict__ Vt)
{
    __shared__ float s[32][33];
    int bn = blockIdx.z, b = bn / NH, n = bn % NH;
    int l0 = blockIdx.x * 32, d0 = blockIdx.y * 32;
    int tx = threadIdx.x, ty = threadIdx.y;
#pragma unroll
    for (int i = 0; i < 32; i += 8)
        s[ty + i][tx] = qkv[(size_t)(b * LSEQ + l0 + ty + i) * NQKV + 2 * DIM + n * HD + d0 + tx];
    __syncthreads();
#pragma unroll
    for (int i = 0; i < 32; i += 8)
        Vt[(size_t)(bn * HD + d0 + ty + i) * LSEQ + l0 + tx] = s[tx][ty + i];
}

// ================= rel-pos bias precompute ======================================
// RH[bn][l][kh] = q[bn][l] . rel_pos_h[qh-kh+31] ; RW similarly
__global__ __launch_bounds__(256) void relbias_kernel(
    const float* __restrict__ Q, const float* __restrict__ rph,
    const float* __restrict__ rpw, float* __restrict__ RH, float* __restrict__ RW)
{
    int idx = blockIdx.x * 256 + threadIdx.x;
    int j = idx & 63;
    int l = (idx >> 6) & (LSEQ - 1);
    int bn = idx >> 16;
    const float* qr = Q + ((size_t)bn * LSEQ + l) * HD;
    int k = j & 31;
    const float* tr = (j < 32) ? (rph + (size_t)((l >> 5) - k + 31) * HD)
                               : (rpw + (size_t)((l & 31) - k + 31) * HD);
    float acc = 0.f;
#pragma unroll
    for (int d = 0; d < HD; d += 4) {
        float4 q4 = *(const float4*)&qr[d];
        float4 t4 = *(const float4*)&tr[d];
        acc = fmaf(q4.x, t4.x, fmaf(q4.y, t4.y, fmaf(q4.z, t4.z, fmaf(q4.w, t4.w, acc))));
    }
    if (j < 32) RH[((size_t)bn * LSEQ + l) * 32 + k] = acc;
    else        RW[((size_t)bn * LSEQ + l) * 32 + k] = acc;
}

// ================= scores GEMM: P = Q@K^T * 0.125 + rh + rw =====================
__global__ __launch_bounds__(256) void gemm_scores(
    const float* __restrict__ Qg, const float* __restrict__ Kg,
    const float* __restrict__ RH, const float* __restrict__ RW,
    float* __restrict__ P)
{
    __shared__ float As[16][132];
    __shared__ float Bs[16][132];
    const int bn = blockIdx.z;
    const float* A = Qg + (size_t)bn * LSEQ * HD;
    const float* Bm = Kg + (size_t)bn * LSEQ * HD;
    float* Pb = P + (size_t)bn * LSEQ * LSEQ;

    const int tid = threadIdx.x;
    const int tx = tid & 15, ty = tid >> 4;
    const int m0 = blockIdx.y * 128, n0 = blockIdx.x * 128;
    const int lr = tid >> 2, lc = (tid & 3) * 4;

    float acc[8][8];
#pragma unroll
    for (int i = 0; i < 8; i++)
#pragma unroll
        for (int j = 0; j < 8; j++) acc[i][j] = 0.f;

    const float* Ar0 = A + (size_t)(m0 + lr) * HD + lc;
    const float* Ar1 = Ar0 + (size_t)64 * HD;
    const float* Br0 = Bm + (size_t)(n0 + lr) * HD + lc;
    const float* Br1 = Br0 + (size_t)64 * HD;

#pragma unroll
    for (int k0 = 0; k0 < HD; k0 += 16) {
        float4 a0 = *(const float4*)(Ar0 + k0);
        float4 a1 = *(const float4*)(Ar1 + k0);
        float4 b0 = *(const float4*)(Br0 + k0);
        float4 b1 = *(const float4*)(Br1 + k0);
        __syncthreads();
        As[lc+0][lr] = a0.x; As[lc+1][lr] = a0.y; As[lc+2][lr] = a0.z; As[lc+3][lr] = a0.w;
        As[lc+0][lr+64] = a1.x; As[lc+1][lr+64] = a1.y; As[lc+2][lr+64] = a1.z; As[lc+3][lr+64] = a1.w;
        Bs[lc+0][lr] = b0.x; Bs[lc+1][lr] = b0.y; Bs[lc+2][lr] = b0.z; Bs[lc+3][lr] = b0.w;
        Bs[lc+0][lr+64] = b1.x; Bs[lc+1][lr+64] = b1.y; Bs[lc+2][lr+64] = b1.z; Bs[lc+3][lr+64] = b1.w;
        __syncthreads();
#pragma unroll
        for (int kk = 0; kk < 16; kk++) {
            float4 xa = *(const float4*)&As[kk][ty * 4];
            float4 xb = *(const float4*)&As[kk][64 + ty * 4];
            float4 ya = *(const float4*)&Bs[kk][tx * 4];
            float4 yb = *(const float4*)&Bs[kk][64 + tx * 4];
            float am[8] = {xa.x, xa.y, xa.z, xa.w, xb.x, xb.y, xb.z, xb.w};
            float bv[8] = {ya.x, ya.y, ya.z, ya.w, yb.x, yb.y, yb.z, yb.w};
#pragma unroll
            for (int i = 0; i < 8; i++)
#pragma unroll
                for (int j = 0; j < 8; j++)
                    acc[i][j] = fmaf(am[i], bv[j], acc[i][j]);
        }
    }

    const int na = n0 + tx * 4, nb = n0 + 64 + tx * 4;
#pragma unroll
    for (int i = 0; i < 8; i++) {
        int m = m0 + ((i < 4) ? (ty * 4 + i) : (64 + ty * 4 + i - 4));
        const float* rhr = RH + ((size_t)bn * LSEQ + m) * 32;
        const float* rwr = RW + ((size_t)bn * LSEQ + m) * 32;
        float rh0 = rhr[na >> 5], rh1 = rhr[nb >> 5];
        float4 rw0 = *(const float4*)&rwr[na & 31];
        float4 rw1 = *(const float4*)&rwr[nb & 31];
        float4 o0 = make_float4(fmaf(acc[i][0], 0.125f, rh0 + rw0.x),
                                fmaf(acc[i][1], 0.125f, rh0 + rw0.y),
                                fmaf(acc[i][2], 0.125f, rh0 + rw0.z),
                                fmaf(acc[i][3], 0.125f, rh0 + rw0.w));
        float4 o1 = make_float4(fmaf(acc[i][4], 0.125f, rh1 + rw1.x),
                                fmaf(acc[i][5], 0.125f, rh1 + rw1.y),
                                fmaf(acc[i][6], 0.125f, rh1 + rw1.z),
                                fmaf(acc[i][7], 0.125f, rh1 + rw1.w));
        *(float4*)&Pb[(size_t)m * LSEQ + na] = o0;
        *(float4*)&Pb[(size_t)m * LSEQ + nb] = o1;
    }
}

// ================= row softmax (FMA-only exp2 poly, no MUFU) ====================
__device__ __forceinline__ float fexp_neg(float x) {  // exp(x), x <= 0
    float t = fmaxf(x * 1.4426950408889634f, -126.0f);
    float fl = floorf(t);
    float f = t - fl;
    float p = 1.5403530e-4f;
    p = fmaf(p, f, 1.3333558e-3f);
    p = fmaf(p, f, 9.6181291e-3f);
    p = fmaf(p, f, 5.5504109e-2f);
    p = fmaf(p, f, 2.4022651e-1f);
    p = fmaf(p, f, 6.9314718e-1f);
    p = fmaf(p, f, 1.0f);
    int i = (int)fl;
    return p * __int_as_float((i + 127) << 23);
}

__global__ __launch_bounds__(256) void softmax_rows(float* __restrict__ P)
{
    __shared__ float rmax[8], rsum[8];
    float* p = P + (size_t)blockIdx.x * LSEQ;
    int tid = threadIdx.x;
    float4 v = ((float4*)p)[tid];
    float m = fmaxf(fmaxf(v.x, v.y), fmaxf(v.z, v.w));
#pragma unroll
    for (int o = 16; o; o >>= 1) m = fmaxf(m, __shfl_xor_sync(0xffffffffu, m, o));
    if ((tid & 31) == 0) rmax[tid >> 5] = m;
    __syncthreads();
    m = rmax[0];
#pragma unroll
    for (int i = 1; i < 8; i++) m = fmaxf(m, rmax[i]);

    v.x = fexp_neg(v.x - m); v.y = fexp_neg(v.y - m);
    v.z = fexp_neg(v.z - m); v.w = fexp_neg(v.w - m);
    float s = (v.x + v.y) + (v.z + v.w);
#pragma unroll
    for (int o = 16; o; o >>= 1) s += __shfl_xor_sync(0xffffffffu, s, o);
    if ((tid & 31) == 0) rsum[tid >> 5] = s;
    __syncthreads();
    s = ((rsum[0] + rsum[1]) + (rsum[2] + rsum[3])) +
        ((rsum[4] + rsum[5]) + (rsum[6] + rsum[7]));
    float r = __fdividef(1.0f, s);
    v.x *= r; v.y *= r; v.z *= r; v.w *= r;
    ((float4*)p)[tid] = v;
}

// ================= AV GEMM: out = P @ V (NT vs Vt), 256x64x1024 =================
__global__ __launch_bounds__(256) void gemm_av(
    const float* __restrict__ P, const float* __restrict__ Vt,
    float* __restrict__ Out)
{
    __shared__ float As[16][260];
    __shared__ float Bs[16][68];
    const int bn = blockIdx.z, b = bn / NH, n = bn % NH;
    const float* A = P + (size_t)bn * LSEQ * LSEQ;
    const float* Bm = Vt + (size_t)bn * HD * LSEQ;

    const int tid = threadIdx.x;
    const int tx = tid & 15, ty = tid >> 4;
    const int m0 = blockIdx.y * 256;
    const int lr = tid >> 2, lc = (tid & 3) * 4;

    float acc[16][4];
#pragma unroll
    for (int i = 0; i < 16; i++)
#pragma unroll
        for (int j = 0; j < 4; j++) acc[i][j] = 0.f;

    for (int k0 = 0; k0 < LSEQ; k0 += 16) {
        float4 a[4];
#pragma unroll
        for (int h = 0; h < 4; h++)
            a[h] = *(const float4*)&A[(size_t)(m0 + lr + 64 * h) * LSEQ + k0 + lc];
        float4 bb = *(const float4*)&Bm[(size_t)lr * LSEQ + k0 + lc];
        __syncthreads();
#pragma unroll
        for (int h = 0; h < 4; h++) {
            As[lc+0][lr + 64*h] = a[h].x; As[lc+1][lr + 64*h] = a[h].y;
            As[lc+2][lr + 64*h] = a[h].z; As[lc+3][lr + 64*h] = a[h].w;
        }
        Bs[lc+0][lr] = bb.x; Bs[lc+1][lr] = bb.y; Bs[lc+2][lr] = bb.z; Bs[lc+3][lr] = bb.w;
        __syncthreads();
#pragma unroll
        for (int kk = 0; kk < 16; kk++) {
            float4 y = *(const float4*)&Bs[kk][tx * 4];
            float bv[4] = {y.x, y.y, y.z, y.w};
#pragma unroll
            for (int h = 0; h < 4; h++) {
                float4 xa = *(const float4*)&As[kk][64 * h + ty * 4];
                float am[4] = {xa.x, xa.y, xa.z, xa.w};
#pragma unroll
                for (int i = 0; i < 4; i++)
#pragma unroll
                    for (int j = 0; j < 4; j++)
                        acc[h * 4 + i][j] = fmaf(am[i], bv[j], acc[h * 4 + i][j]);
            }
        }
    }
#pragma unroll
    for (int h = 0; h < 4; h++)
#pragma unroll
        for (int i = 0; i < 4; i++) {
            int m = m0 + 64 * h + ty * 4 + i;
            *(float4*)&Out[((size_t)(b * LSEQ + m)) * DIM + n * HD + tx * 4] =
                make_float4(acc[h*4+i][0], acc[h*4+i][1], acc[h*4+i][2], acc[h*4+i][3]);
        }
}

// ================= launch ========================================================
extern "C" void kernel_launch(void* const* d_in, const int* in_sizes, int n_in,
                              void* d_out, int out_size)
{
    const float* x      = (const float*)d_in[0];
    const float* qkv_w  = (const float*)d_in[1];
    const float* qkv_b  = (const float*)d_in[2];
    const float* proj_w = (const float*)d_in[3];
    const float* proj_b = (const float*)d_in[4];
    const float* rph    = (const float*)d_in[5];
    const float* rpw    = (const float*)d_in[6];
    float* out = (float*)d_out;

    float *p_qkv, *p_q, *p_k, *p_vt, *p_att, *p_P, *p_rh, *p_rw;
    cudaGetSymbolAddress((void**)&p_qkv, g_qkv);
    cudaGetSymbolAddress((void**)&p_q,   g_q);
    cudaGetSymbolAddress((void**)&p_k,   g_k);
    cudaGetSymbolAddress((void**)&p_vt,  g_vt);
    cudaGetSymbolAddress((void**)&p_att, g_att);
    cudaGetSymbolAddress((void**)&p_P,   g_P);
    cudaGetSymbolAddress((void**)&p_rh,  g_rh);
    cudaGetSymbolAddress((void**)&p_rw,  g_rw);

    // 1) QKV GEMM: (8192x2304) = x(8192x768) @ qkv_w^T + b
    gemm_nt_bias<<<dim3(NQKV / 128, MROWS / 128), 256>>>(
        x, qkv_w, qkv_b, p_qkv, NQKV, DIM);

    // 2) split + rope (q,k)
    {
        const int TOT = NHEADS * LSEQ * (HD / 2);
        rope_split_kernel<<<(TOT + 255) / 256, 256>>>(p_qkv, p_q, p_k);
    }

    // 3) V transpose
    vtrans_kernel<<<dim3(LSEQ / 32, HD / 32, NHEADS), dim3(32, 8)>>>(p_qkv, p_vt);

    // 4) rel-pos bias precompute (uses roped q)
    relbias_kernel<<<NHEADS * LSEQ * 64 / 256, 256>>>(p_q, rph, rpw, p_rh, p_rw);

    // 5) scores GEMM with fused scale + bias epilogue
    gemm_scores<<<dim3(LSEQ / 128, LSEQ / 128, NHEADS), 256>>>(
        p_q, p_k, p_rh, p_rw, p_P);

    // 6) row softmax
    softmax_rows<<<NHEADS * LSEQ, 256>>>(p_P);

    // 7) AV GEMM
    gemm_av<<<dim3(1, LSEQ / 256, NHEADS), 256>>>(p_P, p_vt, p_att);

    // 8) output projection
    gemm_nt_bias<<<dim3(DIM / 128, MROWS / 128), 256>>>(
        p_att, proj_w, proj_b, out, DIM, DIM);
}

// round 6
// speedup vs baseline: 2.3117x; 1.2329x over previous
#include <cuda_runtime.h>
#include <math.h>

// Problem constants
#define BATCH 8
#define HGT 32
#define WID 32
#define DIM 768
#define NH 12
#define HD 64
#define LSEQ 1024
#define MROWS (BATCH*LSEQ)      // 8192
#define NQKV (3*DIM)            // 2304
#define NHEADS (BATCH*NH)       // 96

// ---------------- scratch (static device globals; no allocation) ----------------
__device__ float g_qkv[MROWS * NQKV];                 // (B,L,3*dim)      75 MB
__device__ float g_q[NHEADS * LSEQ * HD];             // roped q          25 MB
__device__ float g_k[NHEADS * LSEQ * HD];             // roped k          25 MB
__device__ float g_vt[NHEADS * HD * LSEQ];            // V transposed     25 MB
__device__ float g_att[MROWS * DIM];                  // attn output      25 MB
__device__ float g_P[NHEADS * LSEQ * LSEQ];           // probs           402 MB
__device__ float g_rh[NHEADS * LSEQ * 32];            // rel_h bias     12.6 MB
__device__ float g_rw[NHEADS * LSEQ * 32];            // rel_w bias     12.6 MB

// ================= generic NT GEMM: C[m,n] = sum_k A[m,k]*B[n,k] (+bias[n]) =====
// 128x128 block tile, BK=16, 256 threads, 8x8 micro-tile, register prefetch.
__global__ __launch_bounds__(256) void gemm_nt_bias(
    const float* __restrict__ A, const float* __restrict__ Bm,
    const float* __restrict__ bias, float* __restrict__ C,
    int Ndim, int Kdim)
{
    __shared__ float As[16][132];
    __shared__ float Bs[16][132];
    const int tid = threadIdx.x;
    const int tx = tid & 15, ty = tid >> 4;
    const int m0 = blockIdx.y * 128, n0 = blockIdx.x * 128;
    const int lr = tid >> 2, lc = (tid & 3) * 4;

    float acc[8][8];
#pragma unroll
    for (int i = 0; i < 8; i++)
#pragma unroll
        for (int j = 0; j < 8; j++) acc[i][j] = 0.f;

    const float* Ar0 = A + (size_t)(m0 + lr) * Kdim + lc;
    const float* Ar1 = Ar0 + (size_t)64 * Kdim;
    const float* Br0 = Bm + (size_t)(n0 + lr) * Kdim + lc;
    const float* Br1 = Br0 + (size_t)64 * Kdim;

    float4 a0 = *(const float4*)(Ar0);
    float4 a1 = *(const float4*)(Ar1);
    float4 b0 = *(const float4*)(Br0);
    float4 b1 = *(const float4*)(Br1);

    for (int k0 = 0; k0 < Kdim; k0 += 16) {
        __syncthreads();
        As[lc+0][lr] = a0.x; As[lc+1][lr] = a0.y; As[lc+2][lr] = a0.z; As[lc+3][lr] = a0.w;
        As[lc+0][lr+64] = a1.x; As[lc+1][lr+64] = a1.y; As[lc+2][lr+64] = a1.z; As[lc+3][lr+64] = a1.w;
        Bs[lc+0][lr] = b0.x; Bs[lc+1][lr] = b0.y; Bs[lc+2][lr] = b0.z; Bs[lc+3][lr] = b0.w;
        Bs[lc+0][lr+64] = b1.x; Bs[lc+1][lr+64] = b1.y; Bs[lc+2][lr+64] = b1.z; Bs[lc+3][lr+64] = b1.w;
        __syncthreads();

        float4 na0, na1, nb0, nb1;
        const bool has = (k0 + 16) < Kdim;
        if (has) {
            na0 = *(const float4*)(Ar0 + k0 + 16);
            na1 = *(const float4*)(Ar1 + k0 + 16);
            nb0 = *(const float4*)(Br0 + k0 + 16);
            nb1 = *(const float4*)(Br1 + k0 + 16);
        }
#pragma unroll
        for (int kk = 0; kk < 16; kk++) {
            float4 xa = *(const float4*)&As[kk][ty * 4];
            float4 xb = *(const float4*)&As[kk][64 + ty * 4];
            float4 ya = *(const float4*)&Bs[kk][tx * 4];
            float4 yb = *(const float4*)&Bs[kk][64 + tx * 4];
            float am[8] = {xa.x, xa.y, xa.z, xa.w, xb.x, xb.y, xb.z, xb.w};
            float bv[8] = {ya.x, ya.y, ya.z, ya.w, yb.x, yb.y, yb.z, yb.w};
#pragma unroll
            for (int i = 0; i < 8; i++)
#pragma unroll
                for (int j = 0; j < 8; j++)
                    acc[i][j] = fmaf(am[i], bv[j], acc[i][j]);
        }
        if (has) { a0 = na0; a1 = na1; b0 = nb0; b1 = nb1; }
    }

    float4 bb0 = make_float4(0.f, 0.f, 0.f, 0.f), bb1 = bb0;
    if (bias) {
        bb0 = *(const float4*)&bias[n0 + tx * 4];
        bb1 = *(const float4*)&bias[n0 + 64 + tx * 4];
    }
#pragma unroll
    for (int i = 0; i < 8; i++) {
        int m = m0 + ((i < 4) ? (ty * 4 + i) : (64 + ty * 4 + i - 4));
        float4 o0 = make_float4(acc[i][0] + bb0.x, acc[i][1] + bb0.y,
                                acc[i][2] + bb0.z, acc[i][3] + bb0.w);
        float4 o1 = make_float4(acc[i][4] + bb1.x, acc[i][5] + bb1.y,
                                acc[i][6] + bb1.z, acc[i][7] + bb1.w);
        *(float4*)&C[(size_t)m * Ndim + n0 + tx * 4] = o0;
        *(float4*)&C[(size_t)m * Ndim + n0 + 64 + tx * 4] = o1;
    }
}

// ================= split qkv + 2D axial RoPE (q,k only) =========================
__global__ __launch_bounds__(256) void rope_split_kernel(
    const float* __restrict__ qkv, float* __restrict__ q, float* __restrict__ k)
{
    int idx = blockIdx.x * blockDim.x + threadIdx.x;
    const int TOT = NHEADS * LSEQ * (HD / 2);
    if (idx >= TOT) return;
    int j = idx & 31;
    int l = (idx >> 5) & (LSEQ - 1);
    int n = (idx >> 15) % NH;
    int b = idx / (32 * LSEQ * NH);

    size_t in_base = ((size_t)(b * LSEQ + l)) * NQKV + n * HD + 2 * j;
    size_t out_base = ((size_t)((b * NH + n) * LSEQ + l)) * HD + 2 * j;

    int i = j & 15;
    float pos = (j < 16) ? (float)(l & 31) : (float)(l >> 5);
    float f = exp2f(-(float)i * (13.287712379549449f / 16.0f));
    float sn, cs;
    sincosf(pos * f, &sn, &cs);

    float2 qa = *(const float2*)&qkv[in_base];
    float2 ka = *(const float2*)&qkv[in_base + DIM];
    float2 qo, ko;
    qo.x = qa.x * cs - qa.y * sn; qo.y = qa.x * sn + qa.y * cs;
    ko.x = ka.x * cs - ka.y * sn; ko.y = ka.x * sn + ka.y * cs;
    *(float2*)&q[out_base] = qo;
    *(float2*)&k[out_base] = ko;
}

// ================= V transpose: (bn, l, d) -> (bn, d, l) ========================
__global__ __launch_bounds__(256) void vtrans_kernel(
    const float* __restrict__ qkv, float* __restrict__ Vt)
{
    __shared__ float s[32][33];
    int bn = blockIdx.z, b = bn / NH, n = bn % NH;
    int l0 = blockIdx.x * 32, d0 = blockIdx.y * 32;
    int tx = threadIdx.x, ty = threadIdx.y;
#pragma unroll
    for (int i = 0; i < 32; i += 8)
        s[ty + i][tx] = qkv[(size_t)(b * LSEQ + l0 + ty + i) * NQKV + 2 * DIM + n * HD + d0 + tx];
    __syncthreads();
#pragma unroll
    for (int i = 0; i < 32; i += 8)
        Vt[(size_t)(bn * HD + d0 + ty + i) * LSEQ + l0 + tx] = s[tx][ty + i];
}

// ================= rel-pos bias precompute (smem-tiled) =========================
// block = (bn, coord, mode): mode 0 -> RH over qh=coord; mode 1 -> RW over qw=coord
// Loads 32x64 q-tile + 32x64 table-tile into smem (coalesced), computes the
// 32x32 dot grid from smem with a conflict-free lane mapping.
__global__ __launch_bounds__(256) void relbias_kernel(
    const float* __restrict__ Q, const float* __restrict__ rph,
    const float* __restrict__ rpw, float* __restrict__ RH, float* __restrict__ RW)
{
    __shared__ float qs[32][68];
    __shared__ float ts[32][68];
    const int bn = blockIdx.x;       // 0..95
    const int coord = blockIdx.y;    // 0..31
    const int mode = blockIdx.z;     // 0: RH, 1: RW
    const int tid = threadIdx.x;

    // stage tiles: thread loads 2 float4 of q row r and table row r
    {
        int r = tid >> 3;            // 0..31
        int c = (tid & 7) * 8;       // 0..56
        int l = (mode == 0) ? (coord * 32 + r) : (r * 32 + coord);
        const float* qrow = Q + ((size_t)bn * LSEQ + l) * HD;
        *(float4*)&qs[r][c]     = *(const float4*)&qrow[c];
        *(float4*)&qs[r][c + 4] = *(const float4*)&qrow[c + 4];
        const float* trow = ((mode == 0) ? rph : rpw) + (size_t)(coord - r + 31) * HD;
        *(float4*)&ts[r][c]     = *(const float4*)&trow[c];
        *(float4*)&ts[r][c + 4] = *(const float4*)&trow[c + 4];
    }
    __syncthreads();

    // compute: thread -> q row qq = tid>>3, k columns {k0, k0+8, k0+16, k0+24}
    const int qq = tid >> 3;
    const int k0 = tid & 7;
    float acc[4] = {0.f, 0.f, 0.f, 0.f};
#pragma unroll
    for (int d = 0; d < HD; d += 4) {
        float4 q4 = *(const float4*)&qs[qq][d];
#pragma unroll
        for (int j = 0; j < 4; j++) {
            float4 t4 = *(const float4*)&ts[k0 + 8 * j][d];
            acc[j] = fmaf(q4.x, t4.x, fmaf(q4.y, t4.y,
                     fmaf(q4.z, t4.z, fmaf(q4.w, t4.w, acc[j]))));
        }
    }
    int lo = (mode == 0) ? (coord * 32 + qq) : (qq * 32 + coord);
    float* dst = ((mode == 0) ? RH : RW) + ((size_t)bn * LSEQ + lo) * 32;
#pragma unroll
    for (int j = 0; j < 4; j++) dst[k0 + 8 * j] = acc[j];
}

// ================= scores GEMM: P = Q@K^T * 0.125 + rh + rw =====================
__global__ __launch_bounds__(256) void gemm_scores(
    const float* __restrict__ Qg, const float* __restrict__ Kg,
    const float* __restrict__ RH, const float* __restrict__ RW,
    float* __restrict__ P)
{
    __shared__ float As[16][132];
    __shared__ float Bs[16][132];
    const int bn = blockIdx.z;
    const float* A = Qg + (size_t)bn * LSEQ * HD;
    const float* Bm = Kg + (size_t)bn * LSEQ * HD;
    float* Pb = P + (size_t)bn * LSEQ * LSEQ;

    const int tid = threadIdx.x;
    const int tx = tid & 15, ty = tid >> 4;
    const int m0 = blockIdx.y * 128, n0 = blockIdx.x * 128;
    const int lr = tid >> 2, lc = (tid & 3) * 4;

    float acc[8][8];
#pragma unroll
    for (int i = 0; i < 8; i++)
#pragma unroll
        for (int j = 0; j < 8; j++) acc[i][j] = 0.f;

    const float* Ar0 = A + (size_t)(m0 + lr) * HD + lc;
    const float* Ar1 = Ar0 + (size_t)64 * HD;
    const float* Br0 = Bm + (size_t)(n0 + lr) * HD + lc;
    const float* Br1 = Br0 + (size_t)64 * HD;

#pragma unroll
    for (int k0 = 0; k0 < HD; k0 += 16) {
        float4 a0 = *(const float4*)(Ar0 + k0);
        float4 a1 = *(const float4*)(Ar1 + k0);
        float4 b0 = *(const float4*)(Br0 + k0);
        float4 b1 = *(const float4*)(Br1 + k0);
        __syncthreads();
        As[lc+0][lr] = a0.x; As[lc+1][lr] = a0.y; As[lc+2][lr] = a0.z; As[lc+3][lr] = a0.w;
        As[lc+0][lr+64] = a1.x; As[lc+1][lr+64] = a1.y; As[lc+2][lr+64] = a1.z; As[lc+3][lr+64] = a1.w;
        Bs[lc+0][lr] = b0.x; Bs[lc+1][lr] = b0.y; Bs[lc+2][lr] = b0.z; Bs[lc+3][lr] = b0.w;
        Bs[lc+0][lr+64] = b1.x; Bs[lc+1][lr+64] = b1.y; Bs[lc+2][lr+64] = b1.z; Bs[lc+3][lr+64] = b1.w;
        __syncthreads();
#pragma unroll
        for (int kk = 0; kk < 16; kk++) {
            float4 xa = *(const float4*)&As[kk][ty * 4];
            float4 xb = *(const float4*)&As[kk][64 + ty * 4];
            float4 ya = *(const float4*)&Bs[kk][tx * 4];
            float4 yb = *(const float4*)&Bs[kk][64 + tx * 4];
            float am[8] = {xa.x, xa.y, xa.z, xa.w, xb.x, xb.y, xb.z, xb.w};
            float bv[8] = {ya.x, ya.y, ya.z, ya.w, yb.x, yb.y, yb.z, yb.w};
#pragma unroll
            for (int i = 0; i < 8; i++)
#pragma unroll
                for (int j = 0; j < 8; j++)
                    acc[i][j] = fmaf(am[i], bv[j], acc[i][j]);
        }
    }

    const int na = n0 + tx * 4, nb = n0 + 64 + tx * 4;
#pragma unroll
    for (int i = 0; i < 8; i++) {
        int m = m0 + ((i < 4) ? (ty * 4 + i) : (64 + ty * 4 + i - 4));
        const float* rhr = RH + ((size_t)bn * LSEQ + m) * 32;
        const float* rwr = RW + ((size_t)bn * LSEQ + m) * 32;
        float rh0 = rhr[na >> 5], rh1 = rhr[nb >> 5];
        float4 rw0 = *(const float4*)&rwr[na & 31];
        float4 rw1 = *(const float4*)&rwr[nb & 31];
        float4 o0 = make_float4(fmaf(acc[i][0], 0.125f, rh0 + rw0.x),
                                fmaf(acc[i][1], 0.125f, rh0 + rw0.y),
                                fmaf(acc[i][2], 0.125f, rh0 + rw0.z),
                                fmaf(acc[i][3], 0.125f, rh0 + rw0.w));
        float4 o1 = make_float4(fmaf(acc[i][4], 0.125f, rh1 + rw1.x),
                                fmaf(acc[i][5], 0.125f, rh1 + rw1.y),
                                fmaf(acc[i][6], 0.125f, rh1 + rw1.z),
                                fmaf(acc[i][7], 0.125f, rh1 + rw1.w));
        *(float4*)&Pb[(size_t)m * LSEQ + na] = o0;
        *(float4*)&Pb[(size_t)m * LSEQ + nb] = o1;
    }
}

// ================= row softmax (FMA-only exp2 poly, no MUFU) ====================
__device__ __forceinline__ float fexp_neg(float x) {  // exp(x), x <= 0
    float t = fmaxf(x * 1.4426950408889634f, -126.0f);
    float fl = floorf(t);
    float f = t - fl;
    float p = 1.5403530e-4f;
    p = fmaf(p, f, 1.3333558e-3f);
    p = fmaf(p, f, 9.6181291e-3f);
    p = fmaf(p, f, 5.5504109e-2f);
    p = fmaf(p, f, 2.4022651e-1f);
    p = fmaf(p, f, 6.9314718e-1f);
    p = fmaf(p, f, 1.0f);
    int i = (int)fl;
    return p * __int_as_float((i + 127) << 23);
}

__global__ __launch_bounds__(256) void softmax_rows(float* __restrict__ P)
{
    __shared__ float rmax[8], rsum[8];
    float* p = P + (size_t)blockIdx.x * LSEQ;
    int tid = threadIdx.x;
    float4 v = ((float4*)p)[tid];
    float m = fmaxf(fmaxf(v.x, v.y), fmaxf(v.z, v.w));
#pragma unroll
    for (int o = 16; o; o >>= 1) m = fmaxf(m, __shfl_xor_sync(0xffffffffu, m, o));
    if ((tid & 31) == 0) rmax[tid >> 5] = m;
    __syncthreads();
    m = rmax[0];
#pragma unroll
    for (int i = 1; i < 8; i++) m = fmaxf(m, rmax[i]);

    v.x = fexp_neg(v.x - m); v.y = fexp_neg(v.y - m);
    v.z = fexp_neg(v.z - m); v.w = fexp_neg(v.w - m);
    float s = (v.x + v.y) + (v.z + v.w);
#pragma unroll
    for (int o = 16; o; o >>= 1) s += __shfl_xor_sync(0xffffffffu, s, o);
    if ((tid & 31) == 0) rsum[tid >> 5] = s;
    __syncthreads();
    s = ((rsum[0] + rsum[1]) + (rsum[2] + rsum[3])) +
        ((rsum[4] + rsum[5]) + (rsum[6] + rsum[7]));
    float r = __fdividef(1.0f, s);
    v.x *= r; v.y *= r; v.z *= r; v.w *= r;
    ((float4*)p)[tid] = v;
}

// ================= AV GEMM: out = P @ V (NT vs Vt), 256x64x1024, prefetch ======
__global__ __launch_bounds__(256) void gemm_av(
    const float* __restrict__ P, const float* __restrict__ Vt,
    float* __restrict__ Out)
{
    __shared__ float As[16][260];
    __shared__ float Bs[16][68];
    const int bn = blockIdx.z, b = bn / NH, n = bn % NH;
    const float* A = P + (size_t)bn * LSEQ * LSEQ;
    const float* Bm = Vt + (size_t)bn * HD * LSEQ;

    const int tid = threadIdx.x;
    const int tx = tid & 15, ty = tid >> 4;
    const int m0 = blockIdx.y * 256;
    const int lr = tid >> 2, lc = (tid & 3) * 4;

    float acc[16][4];
#pragma unroll
    for (int i = 0; i < 16; i++)
#pragma unroll
        for (int j = 0; j < 4; j++) acc[i][j] = 0.f;

    float4 a[4], bb;
#pragma unroll
    for (int h = 0; h < 4; h++)
        a[h] = *(const float4*)&A[(size_t)(m0 + lr + 64 * h) * LSEQ + lc];
    bb = *(const float4*)&Bm[(size_t)lr * LSEQ + lc];

    for (int k0 = 0; k0 < LSEQ; k0 += 16) {
        __syncthreads();
#pragma unroll
        for (int h = 0; h < 4; h++) {
            As[lc+0][lr + 64*h] = a[h].x; As[lc+1][lr + 64*h] = a[h].y;
            As[lc+2][lr + 64*h] = a[h].z; As[lc+3][lr + 64*h] = a[h].w;
        }
        Bs[lc+0][lr] = bb.x; Bs[lc+1][lr] = bb.y; Bs[lc+2][lr] = bb.z; Bs[lc+3][lr] = bb.w;
        __syncthreads();

        float4 na[4], nbb;
        const bool has = (k0 + 16) < LSEQ;
        if (has) {
#pragma unroll
            for (int h = 0; h < 4; h++)
                na[h] = *(const float4*)&A[(size_t)(m0 + lr + 64 * h) * LSEQ + k0 + 16 + lc];
            nbb = *(const float4*)&Bm[(size_t)lr * LSEQ + k0 + 16 + lc];
        }
#pragma unroll
        for (int kk = 0; kk < 16; kk++) {
            float4 y = *(const float4*)&Bs[kk][tx * 4];
            float bv[4] = {y.x, y.y, y.z, y.w};
#pragma unroll
            for (int h = 0; h < 4; h++) {
                float4 xa = *(const float4*)&As[kk][64 * h + ty * 4];
                float am[4] = {xa.x, xa.y, xa.z, xa.w};
#pragma unroll
                for (int i = 0; i < 4; i++)
#pragma unroll
                    for (int j = 0; j < 4; j++)
                        acc[h * 4 + i][j] = fmaf(am[i], bv[j], acc[h * 4 + i][j]);
            }
        }
        if (has) {
#pragma unroll
            for (int h = 0; h < 4; h++) a[h] = na[h];
            bb = nbb;
        }
    }
#pragma unroll
    for (int h = 0; h < 4; h++)
#pragma unroll
        for (int i = 0; i < 4; i++) {
            int m = m0 + 64 * h + ty * 4 + i;
            *(float4*)&Out[((size_t)(b * LSEQ + m)) * DIM + n * HD + tx * 4] =
                make_float4(acc[h*4+i][0], acc[h*4+i][1], acc[h*4+i][2], acc[h*4+i][3]);
        }
}

// ================= launch ========================================================
extern "C" void kernel_launch(void* const* d_in, const int* in_sizes, int n_in,
                              void* d_out, int out_size)
{
    const float* x      = (const float*)d_in[0];
    const float* qkv_w  = (const float*)d_in[1];
    const float* qkv_b  = (const float*)d_in[2];
    const float* proj_w = (const float*)d_in[3];
    const float* proj_b = (const float*)d_in[4];
    const float* rph    = (const float*)d_in[5];
    const float* rpw    = (const float*)d_in[6];
    float* out = (float*)d_out;

    float *p_qkv, *p_q, *p_k, *p_vt, *p_att, *p_P, *p_rh, *p_rw;
    cudaGetSymbolAddress((void**)&p_qkv, g_qkv);
    cudaGetSymbolAddress((void**)&p_q,   g_q);
    cudaGetSymbolAddress((void**)&p_k,   g_k);
    cudaGetSymbolAddress((void**)&p_vt,  g_vt);
    cudaGetSymbolAddress((void**)&p_att, g_att);
    cudaGetSymbolAddress((void**)&p_P,   g_P);
    cudaGetSymbolAddress((void**)&p_rh,  g_rh);
    cudaGetSymbolAddress((void**)&p_rw,  g_rw);

    // 1) QKV GEMM: (8192x2304) = x(8192x768) @ qkv_w^T + b
    gemm_nt_bias<<<dim3(NQKV / 128, MROWS / 128), 256>>>(
        x, qkv_w, qkv_b, p_qkv, NQKV, DIM);

    // 2) split + rope (q,k)
    {
        const int TOT = NHEADS * LSEQ * (HD / 2);
        rope_split_kernel<<<(TOT + 255) / 256, 256>>>(p_qkv, p_q, p_k);
    }

    // 3) V transpose
    vtrans_kernel<<<dim3(LSEQ / 32, HD / 32, NHEADS), dim3(32, 8)>>>(p_qkv, p_vt);

    // 4) rel-pos bias precompute (smem-tiled)
    relbias_kernel<<<dim3(NHEADS, 32, 2), 256>>>(p_q, rph, rpw, p_rh, p_rw);

    // 5) scores GEMM with fused scale + bias epilogue
    gemm_scores<<<dim3(LSEQ / 128, LSEQ / 128, NHEADS), 256>>>(
        p_q, p_k, p_rh, p_rw, p_P);

    // 6) row softmax
    softmax_rows<<<NHEADS * LSEQ, 256>>>(p_P);

    // 7) AV GEMM
    gemm_av<<<dim3(1, LSEQ / 256, NHEADS), 256>>>(p_P, p_vt, p_att);

    // 8) output projection
    gemm_nt_bias<<<dim3(DIM / 128, MROWS / 128), 256>>>(
        p_att, proj_w, proj_b, out, DIM, DIM);
}

// round 8
// speedup vs baseline: 2.8705x; 1.2417x over previous
#include <cuda_runtime.h>
#include <cuda_bf16.h>
#include <math.h>
#include <stdint.h>

// Problem constants
#define BATCH 8
#define HGT 32
#define WID 32
#define DIM 768
#define NH 12
#define HD 64
#define LSEQ 1024
#define MROWS (BATCH*LSEQ)      // 8192
#define NQKV (3*DIM)            // 2304
#define NHEADS (BATCH*NH)       // 96

// ---------------- scratch (static device globals; no allocation) ----------------
__device__ float g_qkv[MROWS * NQKV];
__device__ float g_q[NHEADS * LSEQ * HD];
__device__ float g_k[NHEADS * LSEQ * HD];
__device__ float g_vt[NHEADS * HD * LSEQ];
__device__ float g_P[NHEADS * LSEQ * LSEQ];
__device__ float g_rh[NHEADS * LSEQ * 32];
__device__ float g_rw[NHEADS * LSEQ * 32];
// bf16 split operands for tensor-core GEMMs
__device__ __nv_bfloat16 g_xh[MROWS * DIM];
__device__ __nv_bfloat16 g_xl[MROWS * DIM];
__device__ __nv_bfloat16 g_wqh[NQKV * DIM];
__device__ __nv_bfloat16 g_wql[NQKV * DIM];
__device__ __nv_bfloat16 g_ath[MROWS * DIM];
__device__ __nv_bfloat16 g_atl[MROWS * DIM];
__device__ __nv_bfloat16 g_wph[DIM * DIM];
__device__ __nv_bfloat16 g_wpl[DIM * DIM];

// ================= helpers ======================================================
__device__ __forceinline__ uint32_t smem_u32(const void* p) {
    uint32_t a;
    asm("{ .reg .u64 t; cvta.to.shared.u64 t, %1; cvt.u32.u64 %0, t; }"
        : "=r"(a) : "l"(p));
    return a;
}
#define LDSM_X4(r0, r1, r2, r3, addr) \
    asm volatile("ldmatrix.sync.aligned.m8n8.x4.shared.b16 {%0,%1,%2,%3}, [%4];" \
                 : "=r"(r0), "=r"(r1), "=r"(r2), "=r"(r3) : "r"(addr))
__device__ __forceinline__ void mma_bf16(float* d, const uint32_t* a,
                                         uint32_t b0, uint32_t b1) {
    asm volatile(
        "mma.sync.aligned.m16n8k16.row.col.f32.bf16.bf16.f32 "
        "{%0,%1,%2,%3}, {%4,%5,%6,%7}, {%8,%9}, {%0,%1,%2,%3};"
        : "+f"(d[0]), "+f"(d[1]), "+f"(d[2]), "+f"(d[3])
        : "r"(a[0]), "r"(a[1]), "r"(a[2]), "r"(a[3]), "r"(b0), "r"(b1));
}

// ================= bf16 hi/lo split (elementwise) ===============================
__global__ __launch_bounds__(256) void split_bf16(
    const float4* __restrict__ X, uint32_t* __restrict__ Hi,
    uint32_t* __restrict__ Lo, int n4)
{
    int i = blockIdx.x * 256 + threadIdx.x;
    if (i >= n4) return;
    float4 v = X[i];
    __nv_bfloat16 h0 = __float2bfloat16(v.x), h1 = __float2bfloat16(v.y);
    __nv_bfloat16 h2 = __float2bfloat16(v.z), h3 = __float2bfloat16(v.w);
    __nv_bfloat16 l0 = __float2bfloat16(v.x - __bfloat162float(h0));
    __nv_bfloat16 l1 = __float2bfloat16(v.y - __bfloat162float(h1));
    __nv_bfloat16 l2 = __float2bfloat16(v.z - __bfloat162float(h2));
    __nv_bfloat16 l3 = __float2bfloat16(v.w - __bfloat162float(h3));
    __nv_bfloat162 hA = {h0, h1}, hB = {h2, h3}, lA = {l0, l1}, lB = {l2, l3};
    Hi[2 * i] = *(uint32_t*)&hA; Hi[2 * i + 1] = *(uint32_t*)&hB;
    Lo[2 * i] = *(uint32_t*)&lA; Lo[2 * i + 1] = *(uint32_t*)&lB;
}

// ================= HMMA NT GEMM (3-pass bf16 split) =============================
// C[m,n] = sum_k A[m,k]*B[n,k] + bias[n]; tiles 128x128x32; 256 thr = 8 warps.
#define SSTR 40   // smem row stride in bf16 (80 B: 16B aligned, ldsm conflict-free)

__global__ __launch_bounds__(256) void mma_gemm(
    const __nv_bfloat16* __restrict__ Ah, const __nv_bfloat16* __restrict__ Al,
    const __nv_bfloat16* __restrict__ Bh, const __nv_bfloat16* __restrict__ Bl,
    const float* __restrict__ bias, float* __restrict__ C, int Nd, int Kc)
{
    __shared__ __align__(16) __nv_bfloat16 sA[128 * SSTR];
    __shared__ __align__(16) __nv_bfloat16 sB[128 * SSTR];

    const int tid = threadIdx.x;
    const int lane = tid & 31, wid = tid >> 5;
    const int wm = (wid & 3) * 32;      // warp M offset
    const int wn = (wid >> 2) * 64;     // warp N offset
    const int m0 = blockIdx.y * 128, n0 = blockIdx.x * 128;

    const uint32_t smA = smem_u32(sA), smB = smem_u32(sB);

    // loader: 512 16B-chunks per tile; thread handles chunks tid, tid+256
    const int r0c = tid >> 2, q0c = (tid & 3) * 8;
    const int r1c = (tid + 256) >> 2, q1c = ((tid + 256) & 3) * 8;

    const __nv_bfloat16* Aps[3] = {Ah, Ah, Al};
    const __nv_bfloat16* Bps[3] = {Bh, Bl, Bh};
    const int kpt = Kc / 32;            // iters per pass
    const int tot = 3 * kpt;

    float acc[2][8][4];
#pragma unroll
    for (int mi = 0; mi < 2; mi++)
#pragma unroll
        for (int ni = 0; ni < 8; ni++)
#pragma unroll
            for (int j = 0; j < 4; j++) acc[mi][ni][j] = 0.f;

    float4 fa0, fa1, fb0, fb1;
    {
        const __nv_bfloat16* Ap = Aps[0];
        const __nv_bfloat16* Bp = Bps[0];
        fa0 = *(const float4*)(Ap + (size_t)(m0 + r0c) * Kc + q0c);
        fa1 = *(const float4*)(Ap + (size_t)(m0 + r1c) * Kc + q1c);
        fb0 = *(const float4*)(Bp + (size_t)(n0 + r0c) * Kc + q0c);
        fb1 = *(const float4*)(Bp + (size_t)(n0 + r1c) * Kc + q1c);
    }

    for (int it = 0; it < tot; it++) {
        __syncthreads();
        *(float4*)(sA + r0c * SSTR + q0c) = fa0;
        *(float4*)(sA + r1c * SSTR + q1c) = fa1;
        *(float4*)(sB + r0c * SSTR + q0c) = fb0;
        *(float4*)(sB + r1c * SSTR + q1c) = fb1;
        __syncthreads();

        if (it + 1 < tot) {
            int p = (it + 1) / kpt;
            int k0 = ((it + 1) - p * kpt) * 32;
            const __nv_bfloat16* Ap = Aps[p];
            const __nv_bfloat16* Bp = Bps[p];
            fa0 = *(const float4*)(Ap + (size_t)(m0 + r0c) * Kc + k0 + q0c);
            fa1 = *(const float4*)(Ap + (size_t)(m0 + r1c) * Kc + k0 + q1c);
            fb0 = *(const float4*)(Bp + (size_t)(n0 + r0c) * Kc + k0 + q0c);
            fb1 = *(const float4*)(Bp + (size_t)(n0 + r1c) * Kc + k0 + q1c);
        }

#pragma unroll
        for (int ks = 0; ks < 2; ks++) {
            const int kb = ks * 16;
            uint32_t afr[2][4];
#pragma unroll
            for (int mi = 0; mi < 2; mi++) {
                uint32_t addr = smA +
                    ((wm + mi * 16 + (lane & 15)) * SSTR + kb + ((lane >> 4) * 8)) * 2;
                LDSM_X4(afr[mi][0], afr[mi][1], afr[mi][2], afr[mi][3], addr);
            }
            uint32_t bfr[4][4];
#pragma unroll
            for (int ng = 0; ng < 4; ng++) {
                int row = wn + ng * 16 + (lane & 7) + (((lane >> 4) & 1) * 8);
                int kcol = kb + (((lane >> 3) & 1) * 8);
                uint32_t addr = smB + (row * SSTR + kcol) * 2;
                LDSM_X4(bfr[ng][0], bfr[ng][1], bfr[ng][2], bfr[ng][3], addr);
            }
#pragma unroll
            for (int mi = 0; mi < 2; mi++)
#pragma unroll
                for (int ng = 0; ng < 4; ng++) {
                    mma_bf16(acc[mi][2 * ng + 0], afr[mi], bfr[ng][0], bfr[ng][1]);
                    mma_bf16(acc[mi][2 * ng + 1], afr[mi], bfr[ng][2], bfr[ng][3]);
                }
        }
    }

    // epilogue
#pragma unroll
    for (int mi = 0; mi < 2; mi++)
#pragma unroll
        for (int ni = 0; ni < 8; ni++) {
            int row = m0 + wm + mi * 16 + (lane >> 2);
            int col = n0 + wn + ni * 8 + (lane & 3) * 2;
            float b0 = bias[col], b1 = bias[col + 1];
            float2 o0 = {acc[mi][ni][0] + b0, acc[mi][ni][1] + b1};
            float2 o1 = {acc[mi][ni][2] + b0, acc[mi][ni][3] + b1};
            *(float2*)&C[(size_t)row * Nd + col] = o0;
            *(float2*)&C[(size_t)(row + 8) * Nd + col] = o1;
        }
}

// ================= split qkv + 2D axial RoPE (q,k only) =========================
__global__ __launch_bounds__(256) void rope_split_kernel(
    const float* __restrict__ qkv, float* __restrict__ q, float* __restrict__ k)
{
    int idx = blockIdx.x * blockDim.x + threadIdx.x;
    const int TOT = NHEADS * LSEQ * (HD / 2);
    if (idx >= TOT) return;
    int j = idx & 31;
    int l = (idx >> 5) & (LSEQ - 1);
    int n = (idx >> 15) % NH;
    int b = idx / (32 * LSEQ * NH);

    size_t in_base = ((size_t)(b * LSEQ + l)) * NQKV + n * HD + 2 * j;
    size_t out_base = ((size_t)((b * NH + n) * LSEQ + l)) * HD + 2 * j;

    int i = j & 15;
    float pos = (j < 16) ? (float)(l & 31) : (float)(l >> 5);
    float f = exp2f(-(float)i * (13.287712379549449f / 16.0f));
    float sn, cs;
    sincosf(pos * f, &sn, &cs);

    float2 qa = *(const float2*)&qkv[in_base];
    float2 ka = *(const float2*)&qkv[in_base + DIM];
    float2 qo, ko;
    qo.x = qa.x * cs - qa.y * sn; qo.y = qa.x * sn + qa.y * cs;
    ko.x = ka.x * cs - ka.y * sn; ko.y = ka.x * sn + ka.y * cs;
    *(float2*)&q[out_base] = qo;
    *(float2*)&k[out_base] = ko;
}

// ================= V transpose: (bn, l, d) -> (bn, d, l) ========================
__global__ __launch_bounds__(256) void vtrans_kernel(
    const float* __restrict__ qkv, float* __restrict__ Vt)
{
    __shared__ float s[32][33];
    int bn = blockIdx.z, b = bn / NH, n = bn % NH;
    int l0 = blockIdx.x * 32, d0 = blockIdx.y * 32;
    int tx = threadIdx.x, ty = threadIdx.y;
#pragma unroll
    for (int i = 0; i < 32; i += 8)
        s[ty + i][tx] = qkv[(size_t)(b * LSEQ + l0 + ty + i) * NQKV + 2 * DIM + n * HD + d0 + tx];
    __syncthreads();
#pragma unroll
    for (int i = 0; i < 32; i += 8)
        Vt[(size_t)(bn * HD + d0 + ty + i) * LSEQ + l0 + tx] = s[tx][ty + i];
}

// ================= rel-pos bias precompute (smem-tiled) =========================
__global__ __launch_bounds__(256) void relbias_kernel(
    const float* __restrict__ Q, const float* __restrict__ rph,
    const float* __restrict__ rpw, float* __restrict__ RH, float* __restrict__ RW)
{
    __shared__ float qs[32][68];
    __shared__ float ts[32][68];
    const int bn = blockIdx.x;
    const int coord = blockIdx.y;
    const int mode = blockIdx.z;
    const int tid = threadIdx.x;

    {
        int r = tid >> 3;
        int c = (tid & 7) * 8;
        int l = (mode == 0) ? (coord * 32 + r) : (r * 32 + coord);
        const float* qrow = Q + ((size_t)bn * LSEQ + l) * HD;
        *(float4*)&qs[r][c]     = *(const float4*)&qrow[c];
        *(float4*)&qs[r][c + 4] = *(const float4*)&qrow[c + 4];
        const float* trow = ((mode == 0) ? rph : rpw) + (size_t)(coord - r + 31) * HD;
        *(float4*)&ts[r][c]     = *(const float4*)&trow[c];
        *(float4*)&ts[r][c + 4] = *(const float4*)&trow[c + 4];
    }
    __syncthreads();

    const int qq = tid >> 3;
    const int k0 = tid & 7;
    float acc[4] = {0.f, 0.f, 0.f, 0.f};
#pragma unroll
    for (int d = 0; d < HD; d += 4) {
        float4 q4 = *(const float4*)&qs[qq][d];
#pragma unroll
        for (int j = 0; j < 4; j++) {
            float4 t4 = *(const float4*)&ts[k0 + 8 * j][d];
            acc[j] = fmaf(q4.x, t4.x, fmaf(q4.y, t4.y,
                     fmaf(q4.z, t4.z, fmaf(q4.w, t4.w, acc[j]))));
        }
    }
    int lo = (mode == 0) ? (coord * 32 + qq) : (qq * 32 + coord);
    float* dst = ((mode == 0) ? RH : RW) + ((size_t)bn * LSEQ + lo) * 32;
#pragma unroll
    for (int j = 0; j < 4; j++) dst[k0 + 8 * j] = acc[j];
}

// ================= scores GEMM: P = Q@K^T * 0.125 + rh + rw =====================
__global__ __launch_bounds__(256) void gemm_scores(
    const float* __restrict__ Qg, const float* __restrict__ Kg,
    const float* __restrict__ RH, const float* __restrict__ RW,
    float* __restrict__ P)
{
    __shared__ float As[16][132];
    __shared__ float Bs[16][132];
    const int bn = blockIdx.z;
    const float* A = Qg + (size_t)bn * LSEQ * HD;
    const float* Bm = Kg + (size_t)bn * LSEQ * HD;
    float* Pb = P + (size_t)bn * LSEQ * LSEQ;

    const int tid = threadIdx.x;
    const int tx = tid & 15, ty = tid >> 4;
    const int m0 = blockIdx.y * 128, n0 = blockIdx.x * 128;
    const int lr = tid >> 2, lc = (tid & 3) * 4;

    float acc[8][8];
#pragma unroll
    for (int i = 0; i < 8; i++)
#pragma unroll
        for (int j = 0; j < 8; j++) acc[i][j] = 0.f;

    const float* Ar0 = A + (size_t)(m0 + lr) * HD + lc;
    const float* Ar1 = Ar0 + (size_t)64 * HD;
    const float* Br0 = Bm + (size_t)(n0 + lr) * HD + lc;
    const float* Br1 = Br0 + (size_t)64 * HD;

#pragma unroll
    for (int k0 = 0; k0 < HD; k0 += 16) {
        float4 a0 = *(const float4*)(Ar0 + k0);
        float4 a1 = *(const float4*)(Ar1 + k0);
        float4 b0 = *(const float4*)(Br0 + k0);
        float4 b1 = *(const float4*)(Br1 + k0);
        __syncthreads();
        As[lc+0][lr] = a0.x; As[lc+1][lr] = a0.y; As[lc+2][lr] = a0.z; As[lc+3][lr] = a0.w;
        As[lc+0][lr+64] = a1.x; As[lc+1][lr+64] = a1.y; As[lc+2][lr+64] = a1.z; As[lc+3][lr+64] = a1.w;
        Bs[lc+0][lr] = b0.x; Bs[lc+1][lr] = b0.y; Bs[lc+2][lr] = b0.z; Bs[lc+3][lr] = b0.w;
        Bs[lc+0][lr+64] = b1.x; Bs[lc+1][lr+64] = b1.y; Bs[lc+2][lr+64] = b1.z; Bs[lc+3][lr+64] = b1.w;
        __syncthreads();
#pragma unroll
        for (int kk = 0; kk < 16; kk++) {
            float4 xa = *(const float4*)&As[kk][ty * 4];
            float4 xb = *(const float4*)&As[kk][64 + ty * 4];
            float4 ya = *(const float4*)&Bs[kk][tx * 4];
            float4 yb = *(const float4*)&Bs[kk][64 + tx * 4];
            float am[8] = {xa.x, xa.y, xa.z, xa.w, xb.x, xb.y, xb.z, xb.w};
            float bv[8] = {ya.x, ya.y, ya.z, ya.w, yb.x, yb.y, yb.z, yb.w};
#pragma unroll
            for (int i = 0; i < 8; i++)
#pragma unroll
                for (int j = 0; j < 8; j++)
                    acc[i][j] = fmaf(am[i], bv[j], acc[i][j]);
        }
    }

    const int na = n0 + tx * 4, nb = n0 + 64 + tx * 4;
#pragma unroll
    for (int i = 0; i < 8; i++) {
        int m = m0 + ((i < 4) ? (ty * 4 + i) : (64 + ty * 4 + i - 4));
        const float* rhr = RH + ((size_t)bn * LSEQ + m) * 32;
        const float* rwr = RW + ((size_t)bn * LSEQ + m) * 32;
        float rh0 = rhr[na >> 5], rh1 = rhr[nb >> 5];
        float4 rw0 = *(const float4*)&rwr[na & 31];
        float4 rw1 = *(const float4*)&rwr[nb & 31];
        float4 o0 = make_float4(fmaf(acc[i][0], 0.125f, rh0 + rw0.x),
                                fmaf(acc[i][1], 0.125f, rh0 + rw0.y),
                                fmaf(acc[i][2], 0.125f, rh0 + rw0.z),
                                fmaf(acc[i][3], 0.125f, rh0 + rw0.w));
        float4 o1 = make_float4(fmaf(acc[i][4], 0.125f, rh1 + rw1.x),
                                fmaf(acc[i][5], 0.125f, rh1 + rw1.y),
                                fmaf(acc[i][6], 0.125f, rh1 + rw1.z),
                                fmaf(acc[i][7], 0.125f, rh1 + rw1.w));
        *(float4*)&Pb[(size_t)m * LSEQ + na] = o0;
        *(float4*)&Pb[(size_t)m * LSEQ + nb] = o1;
    }
}

// ================= row softmax (FMA-only exp2 poly, no MUFU) ====================
__device__ __forceinline__ float fexp_neg(float x) {
    float t = fmaxf(x * 1.4426950408889634f, -126.0f);
    float fl = floorf(t);
    float f = t - fl;
    float p = 1.5403530e-4f;
    p = fmaf(p, f, 1.3333558e-3f);
    p = fmaf(p, f, 9.6181291e-3f);
    p = fmaf(p, f, 5.5504109e-2f);
    p = fmaf(p, f, 2.4022651e-1f);
    p = fmaf(p, f, 6.9314718e-1f);
    p = fmaf(p, f, 1.0f);
    int i = (int)fl;
    return p * __int_as_float((i + 127) << 23);
}

__global__ __launch_bounds__(256) void softmax_rows(float* __restrict__ P)
{
    __shared__ float rmax[8], rsum[8];
    float* p = P + (size_t)blockIdx.x * LSEQ;
    int tid = threadIdx.x;
    float4 v = ((float4*)p)[tid];
    float m = fmaxf(fmaxf(v.x, v.y), fmaxf(v.z, v.w));
#pragma unroll
    for (int o = 16; o; o >>= 1) m = fmaxf(m, __shfl_xor_sync(0xffffffffu, m, o));
    if ((tid & 31) == 0) rmax[tid >> 5] = m;
    __syncthreads();
    m = rmax[0];
#pragma unroll
    for (int i = 1; i < 8; i++) m = fmaxf(m, rmax[i]);

    v.x = fexp_neg(v.x - m); v.y = fexp_neg(v.y - m);
    v.z = fexp_neg(v.z - m); v.w = fexp_neg(v.w - m);
    float s = (v.x + v.y) + (v.z + v.w);
#pragma unroll
    for (int o = 16; o; o >>= 1) s += __shfl_xor_sync(0xffffffffu, s, o);
    if ((tid & 31) == 0) rsum[tid >> 5] = s;
    __syncthreads();
    s = ((rsum[0] + rsum[1]) + (rsum[2] + rsum[3])) +
        ((rsum[4] + rsum[5]) + (rsum[6] + rsum[7]));
    float r = __fdividef(1.0f, s);
    v.x *= r; v.y *= r; v.z *= r; v.w *= r;
    ((float4*)p)[tid] = v;
}

// ================= AV GEMM: out = P @ V, epilogue emits bf16 hi/lo ==============
__global__ __launch_bounds__(256) void gemm_av(
    const float* __restrict__ P, const float* __restrict__ Vt,
    __nv_bfloat16* __restrict__ OutH, __nv_bfloat16* __restrict__ OutL)
{
    __shared__ float As[16][260];
    __shared__ float Bs[16][68];
    const int bn = blockIdx.z, b = bn / NH, n = bn % NH;
    const float* A = P + (size_t)bn * LSEQ * LSEQ;
    const float* Bm = Vt + (size_t)bn * HD * LSEQ;

    const int tid = threadIdx.x;
    const int tx = tid & 15, ty = tid >> 4;
    const int m0 = blockIdx.y * 256;
    const int lr = tid >> 2, lc = (tid & 3) * 4;

    float acc[16][4];
#pragma unroll
    for (int i = 0; i < 16; i++)
#pragma unroll
        for (int j = 0; j < 4; j++) acc[i][j] = 0.f;

    float4 a[4], bb;
#pragma unroll
    for (int h = 0; h < 4; h++)
        a[h] = *(const float4*)&A[(size_t)(m0 + lr + 64 * h) * LSEQ + lc];
    bb = *(const float4*)&Bm[(size_t)lr * LSEQ + lc];

    for (int k0 = 0; k0 < LSEQ; k0 += 16) {
        __syncthreads();
#pragma unroll
        for (int h = 0; h < 4; h++) {
            As[lc+0][lr + 64*h] = a[h].x; As[lc+1][lr + 64*h] = a[h].y;
            As[lc+2][lr + 64*h] = a[h].z; As[lc+3][lr + 64*h] = a[h].w;
        }
        Bs[lc+0][lr] = bb.x; Bs[lc+1][lr] = bb.y; Bs[lc+2][lr] = bb.z; Bs[lc+3][lr] = bb.w;
        __syncthreads();

        float4 na[4], nbb;
        const bool has = (k0 + 16) < LSEQ;
        if (has) {
#pragma unroll
            for (int h = 0; h < 4; h++)
                na[h] = *(const float4*)&A[(size_t)(m0 + lr + 64 * h) * LSEQ + k0 + 16 + lc];
            nbb = *(const float4*)&Bm[(size_t)lr * LSEQ + k0 + 16 + lc];
        }
#pragma unroll
        for (int kk = 0; kk < 16; kk++) {
            float4 y = *(const float4*)&Bs[kk][tx * 4];
            float bv[4] = {y.x, y.y, y.z, y.w};
#pragma unroll
            for (int h = 0; h < 4; h++) {
                float4 xa = *(const float4*)&As[kk][64 * h + ty * 4];
                float am[4] = {xa.x, xa.y, xa.z, xa.w};
#pragma unroll
                for (int i = 0; i < 4; i++)
#pragma unroll
                    for (int j = 0; j < 4; j++)
                        acc[h * 4 + i][j] = fmaf(am[i], bv[j], acc[h * 4 + i][j]);
            }
        }
        if (has) {
#pragma unroll
            for (int h = 0; h < 4; h++) a[h] = na[h];
            bb = nbb;
        }
    }
#pragma unroll
    for (int h = 0; h < 4; h++)
#pragma unroll
        for (int i = 0; i < 4; i++) {
            int m = m0 + 64 * h + ty * 4 + i;
            size_t e = ((size_t)(b * LSEQ + m)) * DIM + n * HD + tx * 4;
            float vv[4] = {acc[h*4+i][0], acc[h*4+i][1], acc[h*4+i][2], acc[h*4+i][3]};
            __nv_bfloat16 hh[4], ll[4];
#pragma unroll
            for (int j = 0; j < 4; j++) {
                hh[j] = __float2bfloat16(vv[j]);
                ll[j] = __float2bfloat16(vv[j] - __bfloat162float(hh[j]));
            }
            __nv_bfloat162 h01 = {hh[0], hh[1]}, h23 = {hh[2], hh[3]};
            __nv_bfloat162 l01 = {ll[0], ll[1]}, l23 = {ll[2], ll[3]};
            uint2 uh = {*(uint32_t*)&h01, *(uint32_t*)&h23};
            uint2 ul = {*(uint32_t*)&l01, *(uint32_t*)&l23};
            *(uint2*)&OutH[e] = uh;
            *(uint2*)&OutL[e] = ul;
        }
}

// ================= launch ========================================================
extern "C" void kernel_launch(void* const* d_in, const int* in_sizes, int n_in,
                              void* d_out, int out_size)
{
    const float* x      = (const float*)d_in[0];
    const float* qkv_w  = (const float*)d_in[1];
    const float* qkv_b  = (const float*)d_in[2];
    const float* proj_w = (const float*)d_in[3];
    const float* proj_b = (const float*)d_in[4];
    const float* rph    = (const float*)d_in[5];
    const float* rpw    = (const float*)d_in[6];
    float* out = (float*)d_out;

    float *p_qkv, *p_q, *p_k, *p_vt, *p_P, *p_rh, *p_rw;
    __nv_bfloat16 *p_xh, *p_xl, *p_wqh, *p_wql, *p_ath, *p_atl, *p_wph, *p_wpl;
    cudaGetSymbolAddress((void**)&p_qkv, g_qkv);
    cudaGetSymbolAddress((void**)&p_q,   g_q);
    cudaGetSymbolAddress((void**)&p_k,   g_k);
    cudaGetSymbolAddress((void**)&p_vt,  g_vt);
    cudaGetSymbolAddress((void**)&p_P,   g_P);
    cudaGetSymbolAddress((void**)&p_rh,  g_rh);
    cudaGetSymbolAddress((void**)&p_rw,  g_rw);
    cudaGetSymbolAddress((void**)&p_xh,  g_xh);
    cudaGetSymbolAddress((void**)&p_xl,  g_xl);
    cudaGetSymbolAddress((void**)&p_wqh, g_wqh);
    cudaGetSymbolAddress((void**)&p_wql, g_wql);
    cudaGetSymbolAddress((void**)&p_ath, g_ath);
    cudaGetSymbolAddress((void**)&p_atl, g_atl);
    cudaGetSymbolAddress((void**)&p_wph, g_wph);
    cudaGetSymbolAddress((void**)&p_wpl, g_wpl);

    // 0) bf16 splits of x and weights
    {
        int n4 = MROWS * DIM / 4;
        split_bf16<<<(n4 + 255) / 256, 256>>>((const float4*)x, (uint32_t*)p_xh,
                                              (uint32_t*)p_xl, n4);
        n4 = NQKV * DIM / 4;
        split_bf16<<<(n4 + 255) / 256, 256>>>((const float4*)qkv_w, (uint32_t*)p_wqh,
                                              (uint32_t*)p_wql, n4);
        n4 = DIM * DIM / 4;
        split_bf16<<<(n4 + 255) / 256, 256>>>((const float4*)proj_w, (uint32_t*)p_wph,
                                              (uint32_t*)p_wpl, n4);
    }

    // 1) QKV GEMM (HMMA, 3-pass split): (8192x2304) = x @ qkv_w^T + b
    mma_gemm<<<dim3(NQKV / 128, MROWS / 128), 256>>>(
        p_xh, p_xl, p_wqh, p_wql, qkv_b, p_qkv, NQKV, DIM);

    // 2) split + rope (q,k)
    {
        const int TOT = NHEADS * LSEQ * (HD / 2);
        rope_split_kernel<<<(TOT + 255) / 256, 256>>>(p_qkv, p_q, p_k);
    }

    // 3) V transpose
    vtrans_kernel<<<dim3(LSEQ / 32, HD / 32, NHEADS), dim3(32, 8)>>>(p_qkv, p_vt);

    // 4) rel-pos bias precompute
    relbias_kernel<<<dim3(NHEADS, 32, 2), 256>>>(p_q, rph, rpw, p_rh, p_rw);

    // 5) scores GEMM with fused scale + bias epilogue
    gemm_scores<<<dim3(LSEQ / 128, LSEQ / 128, NHEADS), 256>>>(
        p_q, p_k, p_rh, p_rw, p_P);

    // 6) row softmax
    softmax_rows<<<NHEADS * LSEQ, 256>>>(p_P);

    // 7) AV GEMM (emits bf16 hi/lo for proj)
    gemm_av<<<dim3(1, LSEQ / 256, NHEADS), 256>>>(p_P, p_vt, p_ath, p_atl);

    // 8) output projection (HMMA, 3-pass split)
    mma_gemm<<<dim3(DIM / 128, MROWS / 128), 256>>>(
        p_ath, p_atl, p_wph, p_wpl, proj_b, out, DIM, DIM);
}

// round 11
// speedup vs baseline: 3.0133x; 1.0498x over previous
#include <cuda_runtime.h>
#include <cuda_bf16.h>
#include <math.h>
#include <stdint.h>

// Problem constants
#define BATCH 8
#define HGT 32
#define WID 32
#define DIM 768
#define NH 12
#define HD 64
#define LSEQ 1024
#define MROWS (BATCH*LSEQ)      // 8192
#define NQKV (3*DIM)            // 2304
#define NHEADS (BATCH*NH)       // 96

// ---------------- scratch (static device globals; no allocation) ----------------
__device__ float g_qkv[MROWS * NQKV];
__device__ float g_qf[NHEADS * LSEQ * HD];            // fp32 roped q (for relbias)
__device__ float g_P[NHEADS * LSEQ * LSEQ];           // fp32 logits
__device__ float g_rh[NHEADS * LSEQ * 32];
__device__ float g_rw[NHEADS * LSEQ * 32];
// bf16 split operands
__device__ __nv_bfloat16 g_xh[MROWS * DIM];
__device__ __nv_bfloat16 g_xl[MROWS * DIM];
__device__ __nv_bfloat16 g_wqh[NQKV * DIM];
__device__ __nv_bfloat16 g_wql[NQKV * DIM];
__device__ __nv_bfloat16 g_qh[NHEADS * LSEQ * HD];
__device__ __nv_bfloat16 g_ql[NHEADS * LSEQ * HD];
__device__ __nv_bfloat16 g_kh[NHEADS * LSEQ * HD];
__device__ __nv_bfloat16 g_kl[NHEADS * LSEQ * HD];
__device__ __nv_bfloat16 g_vth[NHEADS * HD * LSEQ];
__device__ __nv_bfloat16 g_vtl[NHEADS * HD * LSEQ];
__device__ __nv_bfloat16 g_Ph[(size_t)NHEADS * LSEQ * LSEQ];
__device__ __nv_bfloat16 g_Pl[(size_t)NHEADS * LSEQ * LSEQ];
__device__ __nv_bfloat16 g_ath[MROWS * DIM];
__device__ __nv_bfloat16 g_atl[MROWS * DIM];
__device__ __nv_bfloat16 g_wph[DIM * DIM];
__device__ __nv_bfloat16 g_wpl[DIM * DIM];

// ================= helpers ======================================================
__device__ __forceinline__ uint32_t smem_u32(const void* p) {
    uint32_t a;
    asm("{ .reg .u64 t; cvta.to.shared.u64 t, %1; cvt.u32.u64 %0, t; }"
        : "=r"(a) : "l"(p));
    return a;
}
#define LDSM_X4(r0, r1, r2, r3, addr) \
    asm volatile("ldmatrix.sync.aligned.m8n8.x4.shared.b16 {%0,%1,%2,%3}, [%4];" \
                 : "=r"(r0), "=r"(r1), "=r"(r2), "=r"(r3) : "r"(addr))
__device__ __forceinline__ void mma_bf16(float* d, const uint32_t* a,
                                         uint32_t b0, uint32_t b1) {
    asm volatile(
        "mma.sync.aligned.m16n8k16.row.col.f32.bf16.bf16.f32 "
        "{%0,%1,%2,%3}, {%4,%5,%6,%7}, {%8,%9}, {%0,%1,%2,%3};"
        : "+f"(d[0]), "+f"(d[1]), "+f"(d[2]), "+f"(d[3])
        : "r"(a[0]), "r"(a[1]), "r"(a[2]), "r"(a[3]), "r"(b0), "r"(b1));
}
__device__ __forceinline__ void split2(float v, __nv_bfloat16& h, __nv_bfloat16& l) {
    h = __float2bfloat16(v);
    l = __float2bfloat16(v - __bfloat162float(h));
}

// ================= bf16 hi/lo split (elementwise) ===============================
__global__ __launch_bounds__(256) void split_bf16(
    const float4* __restrict__ X, uint32_t* __restrict__ Hi,
    uint32_t* __restrict__ Lo, int n4)
{
    int i = blockIdx.x * 256 + threadIdx.x;
    if (i >= n4) return;
    float4 v = X[i];
    __nv_bfloat16 h0, h1, h2, h3, l0, l1, l2, l3;
    split2(v.x, h0, l0); split2(v.y, h1, l1);
    split2(v.z, h2, l2); split2(v.w, h3, l3);
    __nv_bfloat162 hA = {h0, h1}, hB = {h2, h3}, lA = {l0, l1}, lB = {l2, l3};
    Hi[2 * i] = *(uint32_t*)&hA; Hi[2 * i + 1] = *(uint32_t*)&hB;
    Lo[2 * i] = *(uint32_t*)&lA; Lo[2 * i + 1] = *(uint32_t*)&lB;
}

// ================= HMMA NT GEMM (3-pass bf16 split) =============================
#define SSTR 40   // smem row stride in bf16 (80 B: 16B aligned, ldsm conflict-free)

__global__ __launch_bounds__(256) void mma_gemm(
    const __nv_bfloat16* __restrict__ Ah, const __nv_bfloat16* __restrict__ Al,
    const __nv_bfloat16* __restrict__ Bh, const __nv_bfloat16* __restrict__ Bl,
    const float* __restrict__ bias, float* __restrict__ C, int Nd, int Kc)
{
    __shared__ __align__(16) __nv_bfloat16 sA[128 * SSTR];
    __shared__ __align__(16) __nv_bfloat16 sB[128 * SSTR];

    const int tid = threadIdx.x;
    const int lane = tid & 31, wid = tid >> 5;
    const int wm = (wid & 3) * 32;
    const int wn = (wid >> 2) * 64;
    const int m0 = blockIdx.y * 128, n0 = blockIdx.x * 128;

    const uint32_t smA = smem_u32(sA), smB = smem_u32(sB);
    const int r0c = tid >> 2, q0c = (tid & 3) * 8;
    const int r1c = (tid + 256) >> 2, q1c = ((tid + 256) & 3) * 8;

    const __nv_bfloat16* Aps[3] = {Ah, Ah, Al};
    const __nv_bfloat16* Bps[3] = {Bh, Bl, Bh};
    const int kpt = Kc / 32;
    const int tot = 3 * kpt;

    float acc[2][8][4];
#pragma unroll
    for (int mi = 0; mi < 2; mi++)
#pragma unroll
        for (int ni = 0; ni < 8; ni++)
#pragma unroll
            for (int j = 0; j < 4; j++) acc[mi][ni][j] = 0.f;

    float4 fa0, fa1, fb0, fb1;
    fa0 = *(const float4*)(Aps[0] + (size_t)(m0 + r0c) * Kc + q0c);
    fa1 = *(const float4*)(Aps[0] + (size_t)(m0 + r1c) * Kc + q1c);
    fb0 = *(const float4*)(Bps[0] + (size_t)(n0 + r0c) * Kc + q0c);
    fb1 = *(const float4*)(Bps[0] + (size_t)(n0 + r1c) * Kc + q1c);

    for (int it = 0; it < tot; it++) {
        __syncthreads();
        *(float4*)(sA + r0c * SSTR + q0c) = fa0;
        *(float4*)(sA + r1c * SSTR + q1c) = fa1;
        *(float4*)(sB + r0c * SSTR + q0c) = fb0;
        *(float4*)(sB + r1c * SSTR + q1c) = fb1;
        __syncthreads();

        if (it + 1 < tot) {
            int p = (it + 1) / kpt;
            int k0 = ((it + 1) - p * kpt) * 32;
            fa0 = *(const float4*)(Aps[p] + (size_t)(m0 + r0c) * Kc + k0 + q0c);
            fa1 = *(const float4*)(Aps[p] + (size_t)(m0 + r1c) * Kc + k0 + q1c);
            fb0 = *(const float4*)(Bps[p] + (size_t)(n0 + r0c) * Kc + k0 + q0c);
            fb1 = *(const float4*)(Bps[p] + (size_t)(n0 + r1c) * Kc + k0 + q1c);
        }

#pragma unroll
        for (int ks = 0; ks < 2; ks++) {
            const int kb = ks * 16;
            uint32_t afr[2][4];
#pragma unroll
            for (int mi = 0; mi < 2; mi++) {
                uint32_t addr = smA +
                    ((wm + mi * 16 + (lane & 15)) * SSTR + kb + ((lane >> 4) * 8)) * 2;
                LDSM_X4(afr[mi][0], afr[mi][1], afr[mi][2], afr[mi][3], addr);
            }
            uint32_t bfr[4][4];
#pragma unroll
            for (int ng = 0; ng < 4; ng++) {
                int row = wn + ng * 16 + (lane & 7) + (((lane >> 4) & 1) * 8);
                int kcol = kb + (((lane >> 3) & 1) * 8);
                uint32_t addr = smB + (row * SSTR + kcol) * 2;
                LDSM_X4(bfr[ng][0], bfr[ng][1], bfr[ng][2], bfr[ng][3], addr);
            }
#pragma unroll
            for (int mi = 0; mi < 2; mi++)
#pragma unroll
                for (int ng = 0; ng < 4; ng++) {
                    mma_bf16(acc[mi][2 * ng + 0], afr[mi], bfr[ng][0], bfr[ng][1]);
                    mma_bf16(acc[mi][2 * ng + 1], afr[mi], bfr[ng][2], bfr[ng][3]);
                }
        }
    }

#pragma unroll
    for (int mi = 0; mi < 2; mi++)
#pragma unroll
        for (int ni = 0; ni < 8; ni++) {
            int row = m0 + wm + mi * 16 + (lane >> 2);
            int col = n0 + wn + ni * 8 + (lane & 3) * 2;
            float b0 = bias[col], b1 = bias[col + 1];
            float2 o0 = {acc[mi][ni][0] + b0, acc[mi][ni][1] + b1};
            float2 o1 = {acc[mi][ni][2] + b0, acc[mi][ni][3] + b1};
            *(float2*)&C[(size_t)row * Nd + col] = o0;
            *(float2*)&C[(size_t)(row + 8) * Nd + col] = o1;
        }
}

// ================= HMMA scores: P = (Q@K^T)*0.125 + rh + rw (per head) ==========
__global__ __launch_bounds__(256) void mma_scores(
    const __nv_bfloat16* __restrict__ Qh, const __nv_bfloat16* __restrict__ Ql,
    const __nv_bfloat16* __restrict__ Kh, const __nv_bfloat16* __restrict__ Kl,
    const float* __restrict__ RH, const float* __restrict__ RW,
    float* __restrict__ P)
{
    __shared__ __align__(16) __nv_bfloat16 sA[128 * SSTR];
    __shared__ __align__(16) __nv_bfloat16 sB[128 * SSTR];

    const int tid = threadIdx.x;
    const int lane = tid & 31, wid = tid >> 5;
    const int wm = (wid & 3) * 32;
    const int wn = (wid >> 2) * 64;
    const int bn = blockIdx.z;
    const int m0 = blockIdx.y * 128, n0 = blockIdx.x * 128;
    const size_t hb = (size_t)bn * LSEQ * HD;

    const uint32_t smA = smem_u32(sA), smB = smem_u32(sB);
    const int r0c = tid >> 2, q0c = (tid & 3) * 8;
    const int r1c = (tid + 256) >> 2, q1c = ((tid + 256) & 3) * 8;

    const __nv_bfloat16* Aps[3] = {Qh + hb, Qh + hb, Ql + hb};
    const __nv_bfloat16* Bps[3] = {Kh + hb, Kl + hb, Kh + hb};
    const int tot = 6;  // 3 passes x (64/32)

    float acc[2][8][4];
#pragma unroll
    for (int mi = 0; mi < 2; mi++)
#pragma unroll
        for (int ni = 0; ni < 8; ni++)
#pragma unroll
            for (int j = 0; j < 4; j++) acc[mi][ni][j] = 0.f;

    float4 fa0, fa1, fb0, fb1;
    fa0 = *(const float4*)(Aps[0] + (size_t)(m0 + r0c) * HD + q0c);
    fa1 = *(const float4*)(Aps[0] + (size_t)(m0 + r1c) * HD + q1c);
    fb0 = *(const float4*)(Bps[0] + (size_t)(n0 + r0c) * HD + q0c);
    fb1 = *(const float4*)(Bps[0] + (size_t)(n0 + r1c) * HD + q1c);

    for (int it = 0; it < tot; it++) {
        __syncthreads();
        *(float4*)(sA + r0c * SSTR + q0c) = fa0;
        *(float4*)(sA + r1c * SSTR + q1c) = fa1;
        *(float4*)(sB + r0c * SSTR + q0c) = fb0;
        *(float4*)(sB + r1c * SSTR + q1c) = fb1;
        __syncthreads();

        if (it + 1 < tot) {
            int p = (it + 1) >> 1;
            int k0 = ((it + 1) & 1) * 32;
            fa0 = *(const float4*)(Aps[p] + (size_t)(m0 + r0c) * HD + k0 + q0c);
            fa1 = *(const float4*)(Aps[p] + (size_t)(m0 + r1c) * HD + k0 + q1c);
            fb0 = *(const float4*)(Bps[p] + (size_t)(n0 + r0c) * HD + k0 + q0c);
            fb1 = *(const float4*)(Bps[p] + (size_t)(n0 + r1c) * HD + k0 + q1c);
        }

#pragma unroll
        for (int ks = 0; ks < 2; ks++) {
            const int kb = ks * 16;
            uint32_t afr[2][4];
#pragma unroll
            for (int mi = 0; mi < 2; mi++) {
                uint32_t addr = smA +
                    ((wm + mi * 16 + (lane & 15)) * SSTR + kb + ((lane >> 4) * 8)) * 2;
                LDSM_X4(afr[mi][0], afr[mi][1], afr[mi][2], afr[mi][3], addr);
            }
            uint32_t bfr[4][4];
#pragma unroll
            for (int ng = 0; ng < 4; ng++) {
                int row = wn + ng * 16 + (lane & 7) + (((lane >> 4) & 1) * 8);
                int kcol = kb + (((lane >> 3) & 1) * 8);
                uint32_t addr = smB + (row * SSTR + kcol) * 2;
                LDSM_X4(bfr[ng][0], bfr[ng][1], bfr[ng][2], bfr[ng][3], addr);
            }
#pragma unroll
            for (int mi = 0; mi < 2; mi++)
#pragma unroll
                for (int ng = 0; ng < 4; ng++) {
                    mma_bf16(acc[mi][2 * ng + 0], afr[mi], bfr[ng][0], bfr[ng][1]);
                    mma_bf16(acc[mi][2 * ng + 1], afr[mi], bfr[ng][2], bfr[ng][3]);
                }
        }
    }

    float* Pb = P + (size_t)bn * LSEQ * LSEQ;
#pragma unroll
    for (int mi = 0; mi < 2; mi++)
#pragma unroll
        for (int ni = 0; ni < 8; ni++) {
            int row = m0 + wm + mi * 16 + (lane >> 2);
            int col = n0 + wn + ni * 8 + (lane & 3) * 2;
            const float* rh0 = RH + ((size_t)bn * LSEQ + row) * 32;
            const float* rw0 = RW + ((size_t)bn * LSEQ + row) * 32;
            const float* rh1 = rh0 + 8 * 32;
            const float* rw1 = rw0 + 8 * 32;
            float bh0 = rh0[col >> 5], bh1 = rh1[col >> 5];
            int cw = col & 31;
            float2 o0 = {fmaf(acc[mi][ni][0], 0.125f, bh0 + rw0[cw]),
                         fmaf(acc[mi][ni][1], 0.125f, bh0 + rw0[cw + 1])};
            float2 o1 = {fmaf(acc[mi][ni][2], 0.125f, bh1 + rw1[cw]),
                         fmaf(acc[mi][ni][3], 0.125f, bh1 + rw1[cw + 1])};
            *(float2*)&Pb[(size_t)row * LSEQ + col] = o0;
            *(float2*)&Pb[(size_t)(row + 8) * LSEQ + col] = o1;
        }
}

// ================= HMMA AV: att = P @ V (per head, N=64) ========================
__global__ __launch_bounds__(256) void mma_av(
    const __nv_bfloat16* __restrict__ Ph, const __nv_bfloat16* __restrict__ Pl,
    const __nv_bfloat16* __restrict__ Vth, const __nv_bfloat16* __restrict__ Vtl,
    __nv_bfloat16* __restrict__ OutH, __nv_bfloat16* __restrict__ OutL)
{
    __shared__ __align__(16) __nv_bfloat16 sA[128 * SSTR];
    __shared__ __align__(16) __nv_bfloat16 sB[64 * SSTR];

    const int tid = threadIdx.x;
    const int lane = tid & 31, wid = tid >> 5;
    const int wm = (wid & 3) * 32;
    const int wn = (wid >> 2) * 32;   // 2 warp-cols x 32
    const int bn = blockIdx.z, b = bn / NH, n = bn % NH;
    const int m0 = blockIdx.y * 128;
    const size_t pb = (size_t)bn * LSEQ * LSEQ;
    const size_t vb = (size_t)bn * HD * LSEQ;

    const uint32_t smA = smem_u32(sA), smB = smem_u32(sB);
    const int r0c = tid >> 2, q0c = (tid & 3) * 8;
    const int r1c = (tid + 256) >> 2, q1c = ((tid + 256) & 3) * 8;
    const int rB = tid >> 2, qB = (tid & 3) * 8;   // 64 rows x 32 cols: 256 chunks

    const __nv_bfloat16* Aps[3] = {Ph + pb, Ph + pb, Pl + pb};
    const __nv_bfloat16* Bps[3] = {Vth + vb, Vtl + vb, Vth + vb};
    const int kpt = LSEQ / 32;
    const int tot = 3 * kpt;

    float acc[2][4][4];
#pragma unroll
    for (int mi = 0; mi < 2; mi++)
#pragma unroll
        for (int ni = 0; ni < 4; ni++)
#pragma unroll
            for (int j = 0; j < 4; j++) acc[mi][ni][j] = 0.f;

    float4 fa0, fa1, fb0;
    fa0 = *(const float4*)(Aps[0] + (size_t)(m0 + r0c) * LSEQ + q0c);
    fa1 = *(const float4*)(Aps[0] + (size_t)(m0 + r1c) * LSEQ + q1c);
    fb0 = *(const float4*)(Bps[0] + (size_t)rB * LSEQ + qB);

    for (int it = 0; it < tot; it++) {
        __syncthreads();
        *(float4*)(sA + r0c * SSTR + q0c) = fa0;
        *(float4*)(sA + r1c * SSTR + q1c) = fa1;
        *(float4*)(sB + rB * SSTR + qB) = fb0;
        __syncthreads();

        if (it + 1 < tot) {
            int p = (it + 1) / kpt;
            int k0 = ((it + 1) - p * kpt) * 32;
            fa0 = *(const float4*)(Aps[p] + (size_t)(m0 + r0c) * LSEQ + k0 + q0c);
            fa1 = *(const float4*)(Aps[p] + (size_t)(m0 + r1c) * LSEQ + k0 + q1c);
            fb0 = *(const float4*)(Bps[p] + (size_t)rB * LSEQ + k0 + qB);
        }

#pragma unroll
        for (int ks = 0; ks < 2; ks++) {
            const int kb = ks * 16;
            uint32_t afr[2][4];
#pragma unroll
            for (int mi = 0; mi < 2; mi++) {
                uint32_t addr = smA +
                    ((wm + mi * 16 + (lane & 15)) * SSTR + kb + ((lane >> 4) * 8)) * 2;
                LDSM_X4(afr[mi][0], afr[mi][1], afr[mi][2], afr[mi][3], addr);
            }
            uint32_t bfr[2][4];
#pragma unroll
            for (int ng = 0; ng < 2; ng++) {
                int row = wn + ng * 16 + (lane & 7) + (((lane >> 4) & 1) * 8);
                int kcol = kb + (((lane >> 3) & 1) * 8);
                uint32_t addr = smB + (row * SSTR + kcol) * 2;
                LDSM_X4(bfr[ng][0], bfr[ng][1], bfr[ng][2], bfr[ng][3], addr);
            }
#pragma unroll
            for (int mi = 0; mi < 2; mi++)
#pragma unroll
                for (int ng = 0; ng < 2; ng++) {
                    mma_bf16(acc[mi][2 * ng + 0], afr[mi], bfr[ng][0], bfr[ng][1]);
                    mma_bf16(acc[mi][2 * ng + 1], afr[mi], bfr[ng][2], bfr[ng][3]);
                }
        }
    }

#pragma unroll
    for (int mi = 0; mi < 2; mi++)
#pragma unroll
        for (int ni = 0; ni < 4; ni++) {
            int row = m0 + wm + mi * 16 + (lane >> 2);
            int col = wn + ni * 8 + (lane & 3) * 2;
#pragma unroll
            for (int half = 0; half < 2; half++) {
                int r = row + half * 8;
                float v0 = acc[mi][ni][2 * half], v1 = acc[mi][ni][2 * half + 1];
                __nv_bfloat16 h0, h1, l0, l1;
                split2(v0, h0, l0); split2(v1, h1, l1);
                __nv_bfloat162 hp = {h0, h1}, lp = {l0, l1};
                size_t e = ((size_t)(b * LSEQ + r)) * DIM + n * HD + col;
                *(uint32_t*)&OutH[e] = *(uint32_t*)&hp;
                *(uint32_t*)&OutL[e] = *(uint32_t*)&lp;
            }
        }
}

// ================= split qkv + 2D axial RoPE -> fp32 q + bf16 hi/lo q,k =========
__global__ __launch_bounds__(256) void rope_split_kernel(
    const float* __restrict__ qkv, float* __restrict__ qf,
    __nv_bfloat16* __restrict__ qh, __nv_bfloat16* __restrict__ ql,
    __nv_bfloat16* __restrict__ kh, __nv_bfloat16* __restrict__ kl)
{
    int idx = blockIdx.x * blockDim.x + threadIdx.x;
    const int TOT = NHEADS * LSEQ * (HD / 2);
    if (idx >= TOT) return;
    int j = idx & 31;
    int l = (idx >> 5) & (LSEQ - 1);
    int n = (idx >> 15) % NH;
    int b = idx / (32 * LSEQ * NH);

    size_t in_base = ((size_t)(b * LSEQ + l)) * NQKV + n * HD + 2 * j;
    size_t out_base = ((size_t)((b * NH + n) * LSEQ + l)) * HD + 2 * j;

    int i = j & 15;
    float pos = (j < 16) ? (float)(l & 31) : (float)(l >> 5);
    float f = exp2f(-(float)i * (13.287712379549449f / 16.0f));
    float sn, cs;
    sincosf(pos * f, &sn, &cs);

    float2 qa = *(const float2*)&qkv[in_base];
    float2 ka = *(const float2*)&qkv[in_base + DIM];
    float2 qo, ko;
    qo.x = qa.x * cs - qa.y * sn; qo.y = qa.x * sn + qa.y * cs;
    ko.x = ka.x * cs - ka.y * sn; ko.y = ka.x * sn + ka.y * cs;

    *(float2*)&qf[out_base] = qo;
    __nv_bfloat16 h0, h1, l0, l1;
    split2(qo.x, h0, l0); split2(qo.y, h1, l1);
    __nv_bfloat162 qhp = {h0, h1}, qlp = {l0, l1};
    *(uint32_t*)&qh[out_base] = *(uint32_t*)&qhp;
    *(uint32_t*)&ql[out_base] = *(uint32_t*)&qlp;
    split2(ko.x, h0, l0); split2(ko.y, h1, l1);
    __nv_bfloat162 khp = {h0, h1}, klp = {l0, l1};
    *(uint32_t*)&kh[out_base] = *(uint32_t*)&khp;
    *(uint32_t*)&kl[out_base] = *(uint32_t*)&klp;
}

// ================= V transpose -> bf16 hi/lo (bn, d, l) =========================
__global__ __launch_bounds__(256) void vtrans_kernel(
    const float* __restrict__ qkv, __nv_bfloat16* __restrict__ Vth,
    __nv_bfloat16* __restrict__ Vtl)
{
    __shared__ float s[32][33];
    int bn = blockIdx.z, b = bn / NH, n = bn % NH;
    int l0 = blockIdx.x * 32, d0 = blockIdx.y * 32;
    int tx = threadIdx.x, ty = threadIdx.y;
#pragma unroll
    for (int i = 0; i < 32; i += 8)
        s[ty + i][tx] = qkv[(size_t)(b * LSEQ + l0 + ty + i) * NQKV + 2 * DIM + n * HD + d0 + tx];
    __syncthreads();
#pragma unroll
    for (int i = 0; i < 32; i += 8) {
        float v = s[tx][ty + i];
        __nv_bfloat16 h, l;
        split2(v, h, l);
        size_t e = (size_t)(bn * HD + d0 + ty + i) * LSEQ + l0 + tx;
        Vth[e] = h;
        Vtl[e] = l;
    }
}

// ================= rel-pos bias precompute (smem-tiled) =========================
__global__ __launch_bounds__(256) void relbias_kernel(
    const float* __restrict__ Q, const float* __restrict__ rph,
    const float* __restrict__ rpw, float* __restrict__ RH, float* __restrict__ RW)
{
    __shared__ float qs[32][68];
    __shared__ float ts[32][68];
    const int bn = blockIdx.x;
    const int coord = blockIdx.y;
    const int mode = blockIdx.z;
    const int tid = threadIdx.x;

    {
        int r = tid >> 3;
        int c = (tid & 7) * 8;
        int l = (mode == 0) ? (coord * 32 + r) : (r * 32 + coord);
        const float* qrow = Q + ((size_t)bn * LSEQ + l) * HD;
        *(float4*)&qs[r][c]     = *(const float4*)&qrow[c];
        *(float4*)&qs[r][c + 4] = *(const float4*)&qrow[c + 4];
        const float* trow = ((mode == 0) ? rph : rpw) + (size_t)(coord - r + 31) * HD;
        *(float4*)&ts[r][c]     = *(const float4*)&trow[c];
        *(float4*)&ts[r][c + 4] = *(const float4*)&trow[c + 4];
    }
    __syncthreads();

    const int qq = tid >> 3;
    const int k0 = tid & 7;
    float acc[4] = {0.f, 0.f, 0.f, 0.f};
#pragma unroll
    for (int d = 0; d < HD; d += 4) {
        float4 q4 = *(const float4*)&qs[qq][d];
#pragma unroll
        for (int j = 0; j < 4; j++) {
            float4 t4 = *(const float4*)&ts[k0 + 8 * j][d];
            acc[j] = fmaf(q4.x, t4.x, fmaf(q4.y, t4.y,
                     fmaf(q4.z, t4.z, fmaf(q4.w, t4.w, acc[j]))));
        }
    }
    int lo = (mode == 0) ? (coord * 32 + qq) : (qq * 32 + coord);
    float* dst = ((mode == 0) ? RH : RW) + ((size_t)bn * LSEQ + lo) * 32;
#pragma unroll
    for (int j = 0; j < 4; j++) dst[k0 + 8 * j] = acc[j];
}

// ================= row softmax -> bf16 hi/lo probabilities ======================
__device__ __forceinline__ float fexp_neg(float x) {
    float t = fmaxf(x * 1.4426950408889634f, -126.0f);
    float fl = floorf(t);
    float f = t - fl;
    float p = 1.5403530e-4f;
    p = fmaf(p, f, 1.3333558e-3f);
    p = fmaf(p, f, 9.6181291e-3f);
    p = fmaf(p, f, 5.5504109e-2f);
    p = fmaf(p, f, 2.4022651e-1f);
    p = fmaf(p, f, 6.9314718e-1f);
    p = fmaf(p, f, 1.0f);
    int i = (int)fl;
    return p * __int_as_float((i + 127) << 23);
}

__global__ __launch_bounds__(256) void softmax_rows(
    const float* __restrict__ P, __nv_bfloat16* __restrict__ Ph,
    __nv_bfloat16* __restrict__ Pl)
{
    __shared__ float rmax[8], rsum[8];
    const float* p = P + (size_t)blockIdx.x * LSEQ;
    int tid = threadIdx.x;
    float4 v = ((const float4*)p)[tid];
    float m = fmaxf(fmaxf(v.x, v.y), fmaxf(v.z, v.w));
#pragma unroll
    for (int o = 16; o; o >>= 1) m = fmaxf(m, __shfl_xor_sync(0xffffffffu, m, o));
    if ((tid & 31) == 0) rmax[tid >> 5] = m;
    __syncthreads();
    m = rmax[0];
#pragma unroll
    for (int i = 1; i < 8; i++) m = fmaxf(m, rmax[i]);

    v.x = fexp_neg(v.x - m); v.y = fexp_neg(v.y - m);
    v.z = fexp_neg(v.z - m); v.w = fexp_neg(v.w - m);
    float s = (v.x + v.y) + (v.z + v.w);
#pragma unroll
    for (int o = 16; o; o >>= 1) s += __shfl_xor_sync(0xffffffffu, s, o);
    if ((tid & 31) == 0) rsum[tid >> 5] = s;
    __syncthreads();
    s = ((rsum[0] + rsum[1]) + (rsum[2] + rsum[3])) +
        ((rsum[4] + rsum[5]) + (rsum[6] + rsum[7]));
    float r = __fdividef(1.0f, s);
    v.x *= r; v.y *= r; v.z *= r; v.w *= r;

    __nv_bfloat16 h0, h1, h2, h3, l0, l1, l2, l3;
    split2(v.x, h0, l0); split2(v.y, h1, l1);
    split2(v.z, h2, l2); split2(v.w, h3, l3);
    __nv_bfloat162 hA = {h0, h1}, hB = {h2, h3}, lA = {l0, l1}, lB = {l2, l3};
    size_t e = (size_t)blockIdx.x * LSEQ + tid * 4;
    *(uint32_t*)&Ph[e]     = *(uint32_t*)&hA;
    *(uint32_t*)&Ph[e + 2] = *(uint32_t*)&hB;
    *(uint32_t*)&Pl[e]     = *(uint32_t*)&lA;
    *(uint32_t*)&Pl[e + 2] = *(uint32_t*)&lB;
}

// ================= launch ========================================================
extern "C" void kernel_launch(void* const* d_in, const int* in_sizes, int n_in,
                              void* d_out, int out_size)
{
    const float* x      = (const float*)d_in[0];
    const float* qkv_w  = (const float*)d_in[1];
    const float* qkv_b  = (const float*)d_in[2];
    const float* proj_w = (const float*)d_in[3];
    const float* proj_b = (const float*)d_in[4];
    const float* rph    = (const float*)d_in[5];
    const float* rpw    = (const float*)d_in[6];
    float* out = (float*)d_out;

    float *p_qkv, *p_qf, *p_P, *p_rh, *p_rw;
    __nv_bfloat16 *p_xh, *p_xl, *p_wqh, *p_wql, *p_ath, *p_atl, *p_wph, *p_wpl;
    __nv_bfloat16 *p_qh, *p_ql, *p_kh, *p_kl, *p_vth, *p_vtl, *p_Ph, *p_Pl;
    cudaGetSymbolAddress((void**)&p_qkv, g_qkv);
    cudaGetSymbolAddress((void**)&p_qf,  g_qf);
    cudaGetSymbolAddress((void**)&p_P,   g_P);
    cudaGetSymbolAddress((void**)&p_rh,  g_rh);
    cudaGetSymbolAddress((void**)&p_rw,  g_rw);
    cudaGetSymbolAddress((void**)&p_xh,  g_xh);
    cudaGetSymbolAddress((void**)&p_xl,  g_xl);
    cudaGetSymbolAddress((void**)&p_wqh, g_wqh);
    cudaGetSymbolAddress((void**)&p_wql, g_wql);
    cudaGetSymbolAddress((void**)&p_ath, g_ath);
    cudaGetSymbolAddress((void**)&p_atl, g_atl);
    cudaGetSymbolAddress((void**)&p_wph, g_wph);
    cudaGetSymbolAddress((void**)&p_wpl, g_wpl);
    cudaGetSymbolAddress((void**)&p_qh,  g_qh);
    cudaGetSymbolAddress((void**)&p_ql,  g_ql);
    cudaGetSymbolAddress((void**)&p_kh,  g_kh);
    cudaGetSymbolAddress((void**)&p_kl,  g_kl);
    cudaGetSymbolAddress((void**)&p_vth, g_vth);
    cudaGetSymbolAddress((void**)&p_vtl, g_vtl);
    cudaGetSymbolAddress((void**)&p_Ph,  g_Ph);
    cudaGetSymbolAddress((void**)&p_Pl,  g_Pl);

    // 0) bf16 splits of x and weights
    {
        int n4 = MROWS * DIM / 4;
        split_bf16<<<(n4 + 255) / 256, 256>>>((const float4*)x, (uint32_t*)p_xh,
                                              (uint32_t*)p_xl, n4);
        n4 = NQKV * DIM / 4;
        split_bf16<<<(n4 + 255) / 256, 256>>>((const float4*)qkv_w, (uint32_t*)p_wqh,
                                              (uint32_t*)p_wql, n4);
        n4 = DIM * DIM / 4;
        split_bf16<<<(n4 + 255) / 256, 256>>>((const float4*)proj_w, (uint32_t*)p_wph,
                                              (uint32_t*)p_wpl, n4);
    }

    // 1) QKV GEMM (HMMA)
    mma_gemm<<<dim3(NQKV / 128, MROWS / 128), 256>>>(
        p_xh, p_xl, p_wqh, p_wql, qkv_b, p_qkv, NQKV, DIM);

    // 2) split + rope (fp32 q + bf16 hi/lo q,k)
    {
        const int TOT = NHEADS * LSEQ * (HD / 2);
        rope_split_kernel<<<(TOT + 255) / 256, 256>>>(p_qkv, p_qf, p_qh, p_ql,
                                                      p_kh, p_kl);
    }

    // 3) V transpose (bf16 hi/lo)
    vtrans_kernel<<<dim3(LSEQ / 32, HD / 32, NHEADS), dim3(32, 8)>>>(
        p_qkv, p_vth, p_vtl);

    // 4) rel-pos bias precompute
    relbias_kernel<<<dim3(NHEADS, 32, 2), 256>>>(p_qf, rph, rpw, p_rh, p_rw);

    // 5) scores GEMM (HMMA) with fused scale + bias epilogue
    mma_scores<<<dim3(LSEQ / 128, LSEQ / 128, NHEADS), 256>>>(
        p_qh, p_ql, p_kh, p_kl, p_rh, p_rw, p_P);

    // 6) row softmax -> bf16 hi/lo probs
    softmax_rows<<<NHEADS * LSEQ, 256>>>(p_P, p_Ph, p_Pl);

    // 7) AV GEMM (HMMA) -> bf16 hi/lo attention output
    mma_av<<<dim3(1, LSEQ / 128, NHEADS), 256>>>(p_Ph, p_Pl, p_vth, p_vtl,
                                                 p_ath, p_atl);

    // 8) output projection (HMMA)
    mma_gemm<<<dim3(DIM / 128, MROWS / 128), 256>>>(
        p_ath, p_atl, p_wph, p_wpl, proj_b, out, DIM, DIM);
}

// round 13
// speedup vs baseline: 3.6964x; 1.2267x over previous
#include <cuda_runtime.h>
#include <cuda_bf16.h>
#include <math.h>
#include <stdint.h>

// Problem constants
#define BATCH 8
#define HGT 32
#define WID 32
#define DIM 768
#define NH 12
#define HD 64
#define LSEQ 1024
#define MROWS (BATCH*LSEQ)      // 8192
#define NQKV (3*DIM)            // 2304
#define NHEADS (BATCH*NH)       // 96

// ---------------- scratch (static device globals; no allocation) ----------------
__device__ float g_qkv[MROWS * NQKV];
__device__ float g_qf[NHEADS * LSEQ * HD];
__device__ float g_P[NHEADS * LSEQ * LSEQ];
__device__ float g_rh[NHEADS * LSEQ * 32];
__device__ float g_rw[NHEADS * LSEQ * 32];
__device__ __nv_bfloat16 g_xh[MROWS * DIM];
__device__ __nv_bfloat16 g_xl[MROWS * DIM];
__device__ __nv_bfloat16 g_wqh[NQKV * DIM];
__device__ __nv_bfloat16 g_wql[NQKV * DIM];
__device__ __nv_bfloat16 g_qh[NHEADS * LSEQ * HD];
__device__ __nv_bfloat16 g_ql[NHEADS * LSEQ * HD];
__device__ __nv_bfloat16 g_kh[NHEADS * LSEQ * HD];
__device__ __nv_bfloat16 g_kl[NHEADS * LSEQ * HD];
__device__ __nv_bfloat16 g_vth[NHEADS * HD * LSEQ];
__device__ __nv_bfloat16 g_vtl[NHEADS * HD * LSEQ];
__device__ __nv_bfloat16 g_Ph[(size_t)NHEADS * LSEQ * LSEQ];
__device__ __nv_bfloat16 g_Pl[(size_t)NHEADS * LSEQ * LSEQ];
__device__ __nv_bfloat16 g_ath[MROWS * DIM];
__device__ __nv_bfloat16 g_atl[MROWS * DIM];
__device__ __nv_bfloat16 g_wph[DIM * DIM];
__device__ __nv_bfloat16 g_wpl[DIM * DIM];

// ================= helpers ======================================================
__device__ __forceinline__ uint32_t smem_u32(const void* p) {
    uint32_t a;
    asm("{ .reg .u64 t; cvta.to.shared.u64 t, %1; cvt.u32.u64 %0, t; }"
        : "=r"(a) : "l"(p));
    return a;
}
#define LDSM_X4(r0, r1, r2, r3, addr) \
    asm volatile("ldmatrix.sync.aligned.m8n8.x4.shared.b16 {%0,%1,%2,%3}, [%4];" \
                 : "=r"(r0), "=r"(r1), "=r"(r2), "=r"(r3) : "r"(addr))
__device__ __forceinline__ void mma_bf16(float* d, const uint32_t* a,
                                         uint32_t b0, uint32_t b1) {
    asm volatile(
        "mma.sync.aligned.m16n8k16.row.col.f32.bf16.bf16.f32 "
        "{%0,%1,%2,%3}, {%4,%5,%6,%7}, {%8,%9}, {%0,%1,%2,%3};"
        : "+f"(d[0]), "+f"(d[1]), "+f"(d[2]), "+f"(d[3])
        : "r"(a[0]), "r"(a[1]), "r"(a[2]), "r"(a[3]), "r"(b0), "r"(b1));
}
__device__ __forceinline__ void split2(float v, __nv_bfloat16& h, __nv_bfloat16& l) {
    h = __float2bfloat16(v);
    l = __float2bfloat16(v - __bfloat162float(h));
}
__device__ __forceinline__ void cp16(uint32_t s, const void* g) {
    asm volatile("cp.async.cg.shared.global [%0], [%1], 16;" :: "r"(s), "l"(g));
}
#define CP_COMMIT() asm volatile("cp.async.commit_group;" ::: "memory")
#define CP_WAIT0()  asm volatile("cp.async.wait_group 0;" ::: "memory")
#define CP_WAIT1()  asm volatile("cp.async.wait_group 1;" ::: "memory")

#define SSTR 40                     // smem row stride (bf16): 80 B, ldsm conflict-free
#define TILEB (128 * SSTR * 2)      // 10240 B per 128x32 tile
#define TILEB64 (64 * SSTR * 2)     // 5120 B per 64x32 tile

// ================= bf16 hi/lo split (elementwise) ===============================
__global__ __launch_bounds__(256) void split_bf16(
    const float4* __restrict__ X, uint32_t* __restrict__ Hi,
    uint32_t* __restrict__ Lo, int n4)
{
    int i = blockIdx.x * 256 + threadIdx.x;
    if (i >= n4) return;
    float4 v = X[i];
    __nv_bfloat16 h0, h1, h2, h3, l0, l1, l2, l3;
    split2(v.x, h0, l0); split2(v.y, h1, l1);
    split2(v.z, h2, l2); split2(v.w, h3, l3);
    __nv_bfloat162 hA = {h0, h1}, hB = {h2, h3}, lA = {l0, l1}, lB = {l2, l3};
    Hi[2 * i] = *(uint32_t*)&hA; Hi[2 * i + 1] = *(uint32_t*)&hB;
    Lo[2 * i] = *(uint32_t*)&lA; Lo[2 * i + 1] = *(uint32_t*)&lB;
}

// ======== shared compute: 3-product fragment pass over one staged buffer ========
// A tiles 128 rows, B tiles (NB) rows; warp covers wm(32) x wn(64 or 32).
// acc layout: acc[mi][ni][4], NI = wn/8.
template <int NI>
__device__ __forceinline__ void mma_pass(
    uint32_t bAh, uint32_t bAl, uint32_t bBh, uint32_t bBl,
    int wm, int wn, int lane, float acc[2][NI][4])
{
#pragma unroll
    for (int ks = 0; ks < 2; ks++) {
        const int kb = ks * 16;
        uint32_t ah[2][4], al[2][4], bf[NI / 2][4];
        const uint32_t aoff = (((lane & 15)) * SSTR + kb + ((lane >> 4) * 8)) * 2;
#pragma unroll
        for (int mi = 0; mi < 2; mi++) {
            uint32_t ab = ((wm + mi * 16) * SSTR) * 2 + aoff;
            LDSM_X4(ah[mi][0], ah[mi][1], ah[mi][2], ah[mi][3], bAh + ab);
            LDSM_X4(al[mi][0], al[mi][1], al[mi][2], al[mi][3], bAl + ab);
        }
        const uint32_t boff =
            (((lane & 7) + (((lane >> 4) & 1) * 8)) * SSTR + kb + (((lane >> 3) & 1) * 8)) * 2;
#pragma unroll
        for (int ng = 0; ng < NI / 2; ng++) {
            uint32_t bb = ((wn + ng * 16) * SSTR) * 2 + boff;
            LDSM_X4(bf[ng][0], bf[ng][1], bf[ng][2], bf[ng][3], bBh + bb);
        }
        // P0: Ah*Bh ; P2: Al*Bh
#pragma unroll
        for (int mi = 0; mi < 2; mi++)
#pragma unroll
            for (int ng = 0; ng < NI / 2; ng++) {
                mma_bf16(acc[mi][2 * ng + 0], ah[mi], bf[ng][0], bf[ng][1]);
                mma_bf16(acc[mi][2 * ng + 1], ah[mi], bf[ng][2], bf[ng][3]);
                mma_bf16(acc[mi][2 * ng + 0], al[mi], bf[ng][0], bf[ng][1]);
                mma_bf16(acc[mi][2 * ng + 1], al[mi], bf[ng][2], bf[ng][3]);
            }
        // reload B-lo, P1: Ah*Bl
#pragma unroll
        for (int ng = 0; ng < NI / 2; ng++) {
            uint32_t bb = ((wn + ng * 16) * SSTR) * 2 + boff;
            LDSM_X4(bf[ng][0], bf[ng][1], bf[ng][2], bf[ng][3], bBl + bb);
        }
#pragma unroll
        for (int mi = 0; mi < 2; mi++)
#pragma unroll
            for (int ng = 0; ng < NI / 2; ng++) {
                mma_bf16(acc[mi][2 * ng + 0], ah[mi], bf[ng][0], bf[ng][1]);
                mma_bf16(acc[mi][2 * ng + 1], ah[mi], bf[ng][2], bf[ng][3]);
            }
    }
}

// ================= HMMA NT GEMM (4-tile staging, cp.async double-buffer) ========
extern __shared__ __align__(16) char dsm[];

__global__ __launch_bounds__(256) void mma_gemm(
    const __nv_bfloat16* __restrict__ Ah, const __nv_bfloat16* __restrict__ Al,
    const __nv_bfloat16* __restrict__ Bh, const __nv_bfloat16* __restrict__ Bl,
    const float* __restrict__ bias, float* __restrict__ C, int Nd, int Kc)
{
    const int tid = threadIdx.x;
    const int lane = tid & 31, wid = tid >> 5;
    const int wm = (wid & 3) * 32;
    const int wn = (wid >> 2) * 64;
    const int m0 = blockIdx.y * 128, n0 = blockIdx.x * 128;

    const uint32_t base = smem_u32(dsm);
    // chunk mapping: 512 chunks per 128x32 tile; thread does chunks tid, tid+256
    const int r0 = tid >> 2, c0 = (tid & 3) * 8;
    const int r1 = (tid + 256) >> 2, c1 = ((tid + 256) & 3) * 8;
    const uint32_t s0 = (r0 * SSTR + c0) * 2, s1 = (r1 * SSTR + c1) * 2;

    const int kt = Kc / 32;

    float acc[2][8][4];
#pragma unroll
    for (int mi = 0; mi < 2; mi++)
#pragma unroll
        for (int ni = 0; ni < 8; ni++)
#pragma unroll
            for (int j = 0; j < 4; j++) acc[mi][ni][j] = 0.f;

    auto issue = [&](int k0, int buf) {
        uint32_t bb = base + buf * 4 * TILEB;
        cp16(bb + 0 * TILEB + s0, Ah + (size_t)(m0 + r0) * Kc + k0 + c0);
        cp16(bb + 0 * TILEB + s1, Ah + (size_t)(m0 + r1) * Kc + k0 + c1);
        cp16(bb + 1 * TILEB + s0, Al + (size_t)(m0 + r0) * Kc + k0 + c0);
        cp16(bb + 1 * TILEB + s1, Al + (size_t)(m0 + r1) * Kc + k0 + c1);
        cp16(bb + 2 * TILEB + s0, Bh + (size_t)(n0 + r0) * Kc + k0 + c0);
        cp16(bb + 2 * TILEB + s1, Bh + (size_t)(n0 + r1) * Kc + k0 + c1);
        cp16(bb + 3 * TILEB + s0, Bl + (size_t)(n0 + r0) * Kc + k0 + c0);
        cp16(bb + 3 * TILEB + s1, Bl + (size_t)(n0 + r1) * Kc + k0 + c1);
        CP_COMMIT();
    };

    issue(0, 0);
    for (int it = 0; it < kt; it++) {
        if (it + 1 < kt) { issue((it + 1) * 32, (it + 1) & 1); CP_WAIT1(); }
        else CP_WAIT0();
        __syncthreads();
        uint32_t bb = base + (it & 1) * 4 * TILEB;
        mma_pass<8>(bb, bb + TILEB, bb + 2 * TILEB, bb + 3 * TILEB,
                    wm, wn, lane, acc);
        __syncthreads();
    }

#pragma unroll
    for (int mi = 0; mi < 2; mi++)
#pragma unroll
        for (int ni = 0; ni < 8; ni++) {
            int row = m0 + wm + mi * 16 + (lane >> 2);
            int col = n0 + wn + ni * 8 + (lane & 3) * 2;
            float b0 = bias[col], b1 = bias[col + 1];
            float2 o0 = {acc[mi][ni][0] + b0, acc[mi][ni][1] + b1};
            float2 o1 = {acc[mi][ni][2] + b0, acc[mi][ni][3] + b1};
            *(float2*)&C[(size_t)row * Nd + col] = o0;
            *(float2*)&C[(size_t)(row + 8) * Nd + col] = o1;
        }
}

// ================= HMMA scores ==================================================
__global__ __launch_bounds__(256) void mma_scores(
    const __nv_bfloat16* __restrict__ Qh, const __nv_bfloat16* __restrict__ Ql,
    const __nv_bfloat16* __restrict__ Kh, const __nv_bfloat16* __restrict__ Kl,
    const float* __restrict__ RH, const float* __restrict__ RW,
    float* __restrict__ P)
{
    const int tid = threadIdx.x;
    const int lane = tid & 31, wid = tid >> 5;
    const int wm = (wid & 3) * 32;
    const int wn = (wid >> 2) * 64;
    const int bn = blockIdx.z;
    const int m0 = blockIdx.y * 128, n0 = blockIdx.x * 128;
    const size_t hb = (size_t)bn * LSEQ * HD;
    const __nv_bfloat16* Qhp = Qh + hb; const __nv_bfloat16* Qlp = Ql + hb;
    const __nv_bfloat16* Khp = Kh + hb; const __nv_bfloat16* Klp = Kl + hb;

    const uint32_t base = smem_u32(dsm);
    const int r0 = tid >> 2, c0 = (tid & 3) * 8;
    const int r1 = (tid + 256) >> 2, c1 = ((tid + 256) & 3) * 8;
    const uint32_t s0 = (r0 * SSTR + c0) * 2, s1 = (r1 * SSTR + c1) * 2;

    float acc[2][8][4];
#pragma unroll
    for (int mi = 0; mi < 2; mi++)
#pragma unroll
        for (int ni = 0; ni < 8; ni++)
#pragma unroll
            for (int j = 0; j < 4; j++) acc[mi][ni][j] = 0.f;

    auto issue = [&](int k0, int buf) {
        uint32_t bb = base + buf * 4 * TILEB;
        cp16(bb + 0 * TILEB + s0, Qhp + (size_t)(m0 + r0) * HD + k0 + c0);
        cp16(bb + 0 * TILEB + s1, Qhp + (size_t)(m0 + r1) * HD + k0 + c1);
        cp16(bb + 1 * TILEB + s0, Qlp + (size_t)(m0 + r0) * HD + k0 + c0);
        cp16(bb + 1 * TILEB + s1, Qlp + (size_t)(m0 + r1) * HD + k0 + c1);
        cp16(bb + 2 * TILEB + s0, Khp + (size_t)(n0 + r0) * HD + k0 + c0);
        cp16(bb + 2 * TILEB + s1, Khp + (size_t)(n0 + r1) * HD + k0 + c1);
        cp16(bb + 3 * TILEB + s0, Klp + (size_t)(n0 + r0) * HD + k0 + c0);
        cp16(bb + 3 * TILEB + s1, Klp + (size_t)(n0 + r1) * HD + k0 + c1);
        CP_COMMIT();
    };

    issue(0, 0);
    for (int it = 0; it < 2; it++) {
        if (it == 0) { issue(32, 1); CP_WAIT1(); }
        else CP_WAIT0();
        __syncthreads();
        uint32_t bb = base + (it & 1) * 4 * TILEB;
        mma_pass<8>(bb, bb + TILEB, bb + 2 * TILEB, bb + 3 * TILEB,
                    wm, wn, lane, acc);
        __syncthreads();
    }

    float* Pb = P + (size_t)bn * LSEQ * LSEQ;
#pragma unroll
    for (int mi = 0; mi < 2; mi++)
#pragma unroll
        for (int ni = 0; ni < 8; ni++) {
            int row = m0 + wm + mi * 16 + (lane >> 2);
            int col = n0 + wn + ni * 8 + (lane & 3) * 2;
            const float* rh0 = RH + ((size_t)bn * LSEQ + row) * 32;
            const float* rw0 = RW + ((size_t)bn * LSEQ + row) * 32;
            const float* rh1 = rh0 + 8 * 32;
            const float* rw1 = rw0 + 8 * 32;
            float bh0 = rh0[col >> 5], bh1 = rh1[col >> 5];
            int cw = col & 31;
            float2 o0 = {fmaf(acc[mi][ni][0], 0.125f, bh0 + rw0[cw]),
                         fmaf(acc[mi][ni][1], 0.125f, bh0 + rw0[cw + 1])};
            float2 o1 = {fmaf(acc[mi][ni][2], 0.125f, bh1 + rw1[cw]),
                         fmaf(acc[mi][ni][3], 0.125f, bh1 + rw1[cw + 1])};
            *(float2*)&Pb[(size_t)row * LSEQ + col] = o0;
            *(float2*)&Pb[(size_t)(row + 8) * LSEQ + col] = o1;
        }
}

// ================= HMMA AV ======================================================
#define AVBUF (2 * TILEB + 2 * TILEB64)   // Ph, Pl (128x32) + Vh, Vl (64x32)

__global__ __launch_bounds__(256) void mma_av(
    const __nv_bfloat16* __restrict__ Ph, const __nv_bfloat16* __restrict__ Pl,
    const __nv_bfloat16* __restrict__ Vth, const __nv_bfloat16* __restrict__ Vtl,
    __nv_bfloat16* __restrict__ OutH, __nv_bfloat16* __restrict__ OutL)
{
    const int tid = threadIdx.x;
    const int lane = tid & 31, wid = tid >> 5;
    const int wm = (wid & 3) * 32;
    const int wn = (wid >> 2) * 32;
    const int bn = blockIdx.z, b = bn / NH, n = bn % NH;
    const int m0 = blockIdx.y * 128;
    const __nv_bfloat16* Php = Ph + (size_t)bn * LSEQ * LSEQ;
    const __nv_bfloat16* Plp = Pl + (size_t)bn * LSEQ * LSEQ;
    const __nv_bfloat16* Vhp = Vth + (size_t)bn * HD * LSEQ;
    const __nv_bfloat16* Vlp = Vtl + (size_t)bn * HD * LSEQ;

    const uint32_t base = smem_u32(dsm);
    const int r0 = tid >> 2, c0 = (tid & 3) * 8;
    const int r1 = (tid + 256) >> 2, c1 = ((tid + 256) & 3) * 8;
    const uint32_t s0 = (r0 * SSTR + c0) * 2, s1 = (r1 * SSTR + c1) * 2;

    float acc[2][4][4];
#pragma unroll
    for (int mi = 0; mi < 2; mi++)
#pragma unroll
        for (int ni = 0; ni < 4; ni++)
#pragma unroll
            for (int j = 0; j < 4; j++) acc[mi][ni][j] = 0.f;

    auto issue = [&](int k0, int buf) {
        uint32_t bb = base + buf * AVBUF;
        cp16(bb + 0 * TILEB + s0, Php + (size_t)(m0 + r0) * LSEQ + k0 + c0);
        cp16(bb + 0 * TILEB + s1, Php + (size_t)(m0 + r1) * LSEQ + k0 + c1);
        cp16(bb + 1 * TILEB + s0, Plp + (size_t)(m0 + r0) * LSEQ + k0 + c0);
        cp16(bb + 1 * TILEB + s1, Plp + (size_t)(m0 + r1) * LSEQ + k0 + c1);
        cp16(bb + 2 * TILEB + s0, Vhp + (size_t)r0 * LSEQ + k0 + c0);
        cp16(bb + 2 * TILEB + TILEB64 + s0, Vlp + (size_t)r0 * LSEQ + k0 + c0);
        CP_COMMIT();
    };

    const int kt = LSEQ / 32;
    issue(0, 0);
    for (int it = 0; it < kt; it++) {
        if (it + 1 < kt) { issue((it + 1) * 32, (it + 1) & 1); CP_WAIT1(); }
        else CP_WAIT0();
        __syncthreads();
        uint32_t bb = base + (it & 1) * AVBUF;
        mma_pass<4>(bb, bb + TILEB, bb + 2 * TILEB, bb + 2 * TILEB + TILEB64,
                    wm, wn, lane, acc);
        __syncthreads();
    }

#pragma unroll
    for (int mi = 0; mi < 2; mi++)
#pragma unroll
        for (int ni = 0; ni < 4; ni++) {
            int row = m0 + wm + mi * 16 + (lane >> 2);
            int col = wn + ni * 8 + (lane & 3) * 2;
#pragma unroll
            for (int half = 0; half < 2; half++) {
                int r = row + half * 8;
                float v0 = acc[mi][ni][2 * half], v1 = acc[mi][ni][2 * half + 1];
                __nv_bfloat16 h0, h1, l0, l1;
                split2(v0, h0, l0); split2(v1, h1, l1);
                __nv_bfloat162 hp = {h0, h1}, lp = {l0, l1};
                size_t e = ((size_t)(b * LSEQ + r)) * DIM + n * HD + col;
                *(uint32_t*)&OutH[e] = *(uint32_t*)&hp;
                *(uint32_t*)&OutL[e] = *(uint32_t*)&lp;
            }
        }
}

// ================= split qkv + 2D axial RoPE ====================================
__global__ __launch_bounds__(256) void rope_split_kernel(
    const float* __restrict__ qkv, float* __restrict__ qf,
    __nv_bfloat16* __restrict__ qh, __nv_bfloat16* __restrict__ ql,
    __nv_bfloat16* __restrict__ kh, __nv_bfloat16* __restrict__ kl)
{
    int idx = blockIdx.x * blockDim.x + threadIdx.x;
    const int TOT = NHEADS * LSEQ * (HD / 2);
    if (idx >= TOT) return;
    int j = idx & 31;
    int l = (idx >> 5) & (LSEQ - 1);
    int n = (idx >> 15) % NH;
    int b = idx / (32 * LSEQ * NH);

    size_t in_base = ((size_t)(b * LSEQ + l)) * NQKV + n * HD + 2 * j;
    size_t out_base = ((size_t)((b * NH + n) * LSEQ + l)) * HD + 2 * j;

    int i = j & 15;
    float pos = (j < 16) ? (float)(l & 31) : (float)(l >> 5);
    float f = exp2f(-(float)i * (13.287712379549449f / 16.0f));
    float sn, cs;
    sincosf(pos * f, &sn, &cs);

    float2 qa = *(const float2*)&qkv[in_base];
    float2 ka = *(const float2*)&qkv[in_base + DIM];
    float2 qo, ko;
    qo.x = qa.x * cs - qa.y * sn; qo.y = qa.x * sn + qa.y * cs;
    ko.x = ka.x * cs - ka.y * sn; ko.y = ka.x * sn + ka.y * cs;

    *(float2*)&qf[out_base] = qo;
    __nv_bfloat16 h0, h1, l0, l1;
    split2(qo.x, h0, l0); split2(qo.y, h1, l1);
    __nv_bfloat162 qhp = {h0, h1}, qlp = {l0, l1};
    *(uint32_t*)&qh[out_base] = *(uint32_t*)&qhp;
    *(uint32_t*)&ql[out_base] = *(uint32_t*)&qlp;
    split2(ko.x, h0, l0); split2(ko.y, h1, l1);
    __nv_bfloat162 khp = {h0, h1}, klp = {l0, l1};
    *(uint32_t*)&kh[out_base] = *(uint32_t*)&khp;
    *(uint32_t*)&kl[out_base] = *(uint32_t*)&klp;
}

// ================= V transpose -> bf16 hi/lo ====================================
__global__ __launch_bounds__(256) void vtrans_kernel(
    const float* __restrict__ qkv, __nv_bfloat16* __restrict__ Vth,
    __nv_bfloat16* __restrict__ Vtl)
{
    __shared__ float s[32][33];
    int bn = blockIdx.z, b = bn / NH, n = bn % NH;
    int l0 = blockIdx.x * 32, d0 = blockIdx.y * 32;
    int tx = threadIdx.x, ty = threadIdx.y;
#pragma unroll
    for (int i = 0; i < 32; i += 8)
        s[ty + i][tx] = qkv[(size_t)(b * LSEQ + l0 + ty + i) * NQKV + 2 * DIM + n * HD + d0 + tx];
    __syncthreads();
#pragma unroll
    for (int i = 0; i < 32; i += 8) {
        float v = s[tx][ty + i];
        __nv_bfloat16 h, l;
        split2(v, h, l);
        size_t e = (size_t)(bn * HD + d0 + ty + i) * LSEQ + l0 + tx;
        Vth[e] = h;
        Vtl[e] = l;
    }
}

// ================= rel-pos bias precompute ======================================
__global__ __launch_bounds__(256) void relbias_kernel(
    const float* __restrict__ Q, const float* __restrict__ rph,
    const float* __restrict__ rpw, float* __restrict__ RH, float* __restrict__ RW)
{
    __shared__ float qs[32][68];
    __shared__ float ts[32][68];
    const int bn = blockIdx.x;
    const int coord = blockIdx.y;
    const int mode = blockIdx.z;
    const int tid = threadIdx.x;

    {
        int r = tid >> 3;
        int c = (tid & 7) * 8;
        int l = (mode == 0) ? (coord * 32 + r) : (r * 32 + coord);
        const float* qrow = Q + ((size_t)bn * LSEQ + l) * HD;
        *(float4*)&qs[r][c]     = *(const float4*)&qrow[c];
        *(float4*)&qs[r][c + 4] = *(const float4*)&qrow[c + 4];
        const float* trow = ((mode == 0) ? rph : rpw) + (size_t)(coord - r + 31) * HD;
        *(float4*)&ts[r][c]     = *(const float4*)&trow[c];
        *(float4*)&ts[r][c + 4] = *(const float4*)&trow[c + 4];
    }
    __syncthreads();

    const int qq = tid >> 3;
    const int k0 = tid & 7;
    float acc[4] = {0.f, 0.f, 0.f, 0.f};
#pragma unroll
    for (int d = 0; d < HD; d += 4) {
        float4 q4 = *(const float4*)&qs[qq][d];
#pragma unroll
        for (int j = 0; j < 4; j++) {
            float4 t4 = *(const float4*)&ts[k0 + 8 * j][d];
            acc[j] = fmaf(q4.x, t4.x, fmaf(q4.y, t4.y,
                     fmaf(q4.z, t4.z, fmaf(q4.w, t4.w, acc[j]))));
        }
    }
    int lo = (mode == 0) ? (coord * 32 + qq) : (qq * 32 + coord);
    float* dst = ((mode == 0) ? RH : RW) + ((size_t)bn * LSEQ + lo) * 32;
#pragma unroll
    for (int j = 0; j < 4; j++) dst[k0 + 8 * j] = acc[j];
}

// ================= row softmax -> bf16 hi/lo probabilities ======================
__device__ __forceinline__ float fexp_neg(float x) {
    float t = fmaxf(x * 1.4426950408889634f, -126.0f);
    float fl = floorf(t);
    float f = t - fl;
    float p = 1.5403530e-4f;
    p = fmaf(p, f, 1.3333558e-3f);
    p = fmaf(p, f, 9.6181291e-3f);
    p = fmaf(p, f, 5.5504109e-2f);
    p = fmaf(p, f, 2.4022651e-1f);
    p = fmaf(p, f, 6.9314718e-1f);
    p = fmaf(p, f, 1.0f);
    int i = (int)fl;
    return p * __int_as_float((i + 127) << 23);
}

__global__ __launch_bounds__(256) void softmax_rows(
    const float* __restrict__ P, __nv_bfloat16* __restrict__ Ph,
    __nv_bfloat16* __restrict__ Pl)
{
    __shared__ float rmax[8], rsum[8];
    const float* p = P + (size_t)blockIdx.x * LSEQ;
    int tid = threadIdx.x;
    float4 v = ((const float4*)p)[tid];
    float m = fmaxf(fmaxf(v.x, v.y), fmaxf(v.z, v.w));
#pragma unroll
    for (int o = 16; o; o >>= 1) m = fmaxf(m, __shfl_xor_sync(0xffffffffu, m, o));
    if ((tid & 31) == 0) rmax[tid >> 5] = m;
    __syncthreads();
    m = rmax[0];
#pragma unroll
    for (int i = 1; i < 8; i++) m = fmaxf(m, rmax[i]);

    v.x = fexp_neg(v.x - m); v.y = fexp_neg(v.y - m);
    v.z = fexp_neg(v.z - m); v.w = fexp_neg(v.w - m);
    float s = (v.x + v.y) + (v.z + v.w);
#pragma unroll
    for (int o = 16; o; o >>= 1) s += __shfl_xor_sync(0xffffffffu, s, o);
    if ((tid & 31) == 0) rsum[tid >> 5] = s;
    __syncthreads();
    s = ((rsum[0] + rsum[1]) + (rsum[2] + rsum[3])) +
        ((rsum[4] + rsum[5]) + (rsum[6] + rsum[7]));
    float r = __fdividef(1.0f, s);
    v.x *= r; v.y *= r; v.z *= r; v.w *= r;

    __nv_bfloat16 h0, h1, h2, h3, l0, l1, l2, l3;
    split2(v.x, h0, l0); split2(v.y, h1, l1);
    split2(v.z, h2, l2); split2(v.w, h3, l3);
    __nv_bfloat162 hA = {h0, h1}, hB = {h2, h3}, lA = {l0, l1}, lB = {l2, l3};
    size_t e = (size_t)blockIdx.x * LSEQ + tid * 4;
    *(uint32_t*)&Ph[e]     = *(uint32_t*)&hA;
    *(uint32_t*)&Ph[e + 2] = *(uint32_t*)&hB;
    *(uint32_t*)&Pl[e]     = *(uint32_t*)&lA;
    *(uint32_t*)&Pl[e + 2] = *(uint32_t*)&lB;
}

// ================= launch ========================================================
extern "C" void kernel_launch(void* const* d_in, const int* in_sizes, int n_in,
                              void* d_out, int out_size)
{
    const float* x      = (const float*)d_in[0];
    const float* qkv_w  = (const float*)d_in[1];
    const float* qkv_b  = (const float*)d_in[2];
    const float* proj_w = (const float*)d_in[3];
    const float* proj_b = (const float*)d_in[4];
    const float* rph    = (const float*)d_in[5];
    const float* rpw    = (const float*)d_in[6];
    float* out = (float*)d_out;

    float *p_qkv, *p_qf, *p_P, *p_rh, *p_rw;
    __nv_bfloat16 *p_xh, *p_xl, *p_wqh, *p_wql, *p_ath, *p_atl, *p_wph, *p_wpl;
    __nv_bfloat16 *p_qh, *p_ql, *p_kh, *p_kl, *p_vth, *p_vtl, *p_Ph, *p_Pl;
    cudaGetSymbolAddress((void**)&p_qkv, g_qkv);
    cudaGetSymbolAddress((void**)&p_qf,  g_qf);
    cudaGetSymbolAddress((void**)&p_P,   g_P);
    cudaGetSymbolAddress((void**)&p_rh,  g_rh);
    cudaGetSymbolAddress((void**)&p_rw,  g_rw);
    cudaGetSymbolAddress((void**)&p_xh,  g_xh);
    cudaGetSymbolAddress((void**)&p_xl,  g_xl);
    cudaGetSymbolAddress((void**)&p_wqh, g_wqh);
    cudaGetSymbolAddress((void**)&p_wql, g_wql);
    cudaGetSymbolAddress((void**)&p_ath, g_ath);
    cudaGetSymbolAddress((void**)&p_atl, g_atl);
    cudaGetSymbolAddress((void**)&p_wph, g_wph);
    cudaGetSymbolAddress((void**)&p_wpl, g_wpl);
    cudaGetSymbolAddress((void**)&p_qh,  g_qh);
    cudaGetSymbolAddress((void**)&p_ql,  g_ql);
    cudaGetSymbolAddress((void**)&p_kh,  g_kh);
    cudaGetSymbolAddress((void**)&p_kl,  g_kl);
    cudaGetSymbolAddress((void**)&p_vth, g_vth);
    cudaGetSymbolAddress((void**)&p_vtl, g_vtl);
    cudaGetSymbolAddress((void**)&p_Ph,  g_Ph);
    cudaGetSymbolAddress((void**)&p_Pl,  g_Pl);

    const int GEMM_SMEM = 2 * 4 * TILEB;   // 81920
    const int AV_SMEM   = 2 * AVBUF;       // 61440
    cudaFuncSetAttribute(mma_gemm, cudaFuncAttributeMaxDynamicSharedMemorySize, GEMM_SMEM);
    cudaFuncSetAttribute(mma_scores, cudaFuncAttributeMaxDynamicSharedMemorySize, GEMM_SMEM);
    cudaFuncSetAttribute(mma_av, cudaFuncAttributeMaxDynamicSharedMemorySize, AV_SMEM);

    // 0) bf16 splits of x and weights
    {
        int n4 = MROWS * DIM / 4;
        split_bf16<<<(n4 + 255) / 256, 256>>>((const float4*)x, (uint32_t*)p_xh,
                                              (uint32_t*)p_xl, n4);
        n4 = NQKV * DIM / 4;
        split_bf16<<<(n4 + 255) / 256, 256>>>((const float4*)qkv_w, (uint32_t*)p_wqh,
                                              (uint32_t*)p_wql, n4);
        n4 = DIM * DIM / 4;
        split_bf16<<<(n4 + 255) / 256, 256>>>((const float4*)proj_w, (uint32_t*)p_wph,
                                              (uint32_t*)p_wpl, n4);
    }

    // 1) QKV GEMM (HMMA)
    mma_gemm<<<dim3(NQKV / 128, MROWS / 128), 256, GEMM_SMEM>>>(
        p_xh, p_xl, p_wqh, p_wql, qkv_b, p_qkv, NQKV, DIM);

    // 2) split + rope
    {
        const int TOT = NHEADS * LSEQ * (HD / 2);
        rope_split_kernel<<<(TOT + 255) / 256, 256>>>(p_qkv, p_qf, p_qh, p_ql,
                                                      p_kh, p_kl);
    }

    // 3) V transpose
    vtrans_kernel<<<dim3(LSEQ / 32, HD / 32, NHEADS), dim3(32, 8)>>>(
        p_qkv, p_vth, p_vtl);

    // 4) rel-pos bias precompute
    relbias_kernel<<<dim3(NHEADS, 32, 2), 256>>>(p_qf, rph, rpw, p_rh, p_rw);

    // 5) scores GEMM (HMMA)
    mma_scores<<<dim3(LSEQ / 128, LSEQ / 128, NHEADS), 256, GEMM_SMEM>>>(
        p_qh, p_ql, p_kh, p_kl, p_rh, p_rw, p_P);

    // 6) row softmax -> bf16 hi/lo probs
    softmax_rows<<<NHEADS * LSEQ, 256>>>(p_P, p_Ph, p_Pl);

    // 7) AV GEMM (HMMA)
    mma_av<<<dim3(1, LSEQ / 128, NHEADS), 256, AV_SMEM>>>(p_Ph, p_Pl, p_vth, p_vtl,
                                                          p_ath, p_atl);

    // 8) output projection (HMMA)
    mma_gemm<<<dim3(DIM / 128, MROWS / 128), 256, GEMM_SMEM>>>(
        p_ath, p_atl, p_wph, p_wpl, proj_b, out, DIM, DIM);
}

// round 15
// speedup vs baseline: 4.0373x; 1.0922x over previous
#include <cuda_runtime.h>
#include <cuda_bf16.h>
#include <math.h>
#include <stdint.h>

// Problem constants
#define BATCH 8
#define HGT 32
#define WID 32
#define DIM 768
#define NH 12
#define HD 64
#define LSEQ 1024
#define MROWS (BATCH*LSEQ)      // 8192
#define NQKV (3*DIM)            // 2304
#define NHEADS (BATCH*NH)       // 96

// ---------------- scratch (static device globals; no allocation) ----------------
__device__ float g_qkv[MROWS * NQKV];
__device__ float g_qf[NHEADS * LSEQ * HD];
__device__ float g_P[NHEADS * LSEQ * LSEQ];
__device__ float g_rh[NHEADS * LSEQ * 32];
__device__ float g_rw[NHEADS * LSEQ * 32];
__device__ __nv_bfloat16 g_xh[MROWS * DIM];
__device__ __nv_bfloat16 g_xl[MROWS * DIM];
__device__ __nv_bfloat16 g_wqh[NQKV * DIM];
__device__ __nv_bfloat16 g_wql[NQKV * DIM];
__device__ __nv_bfloat16 g_qh[NHEADS * LSEQ * HD];
__device__ __nv_bfloat16 g_ql[NHEADS * LSEQ * HD];
__device__ __nv_bfloat16 g_kh[NHEADS * LSEQ * HD];
__device__ __nv_bfloat16 g_kl[NHEADS * LSEQ * HD];
__device__ __nv_bfloat16 g_vth[NHEADS * HD * LSEQ];
__device__ __nv_bfloat16 g_vtl[NHEADS * HD * LSEQ];
__device__ __nv_bfloat16 g_Ph[(size_t)NHEADS * LSEQ * LSEQ];
__device__ __nv_bfloat16 g_Pl[(size_t)NHEADS * LSEQ * LSEQ];
__device__ __nv_bfloat16 g_ath[MROWS * DIM];
__device__ __nv_bfloat16 g_atl[MROWS * DIM];
__device__ __nv_bfloat16 g_wph[DIM * DIM];
__device__ __nv_bfloat16 g_wpl[DIM * DIM];

// ================= helpers ======================================================
__device__ __forceinline__ uint32_t smem_u32(const void* p) {
    uint32_t a;
    asm("{ .reg .u64 t; cvta.to.shared.u64 t, %1; cvt.u32.u64 %0, t; }"
        : "=r"(a) : "l"(p));
    return a;
}
#define LDSM_X4(r0, r1, r2, r3, addr) \
    asm volatile("ldmatrix.sync.aligned.m8n8.x4.shared.b16 {%0,%1,%2,%3}, [%4];" \
                 : "=r"(r0), "=r"(r1), "=r"(r2), "=r"(r3) : "r"(addr))
__device__ __forceinline__ void mma_bf16(float* d, const uint32_t* a,
                                         uint32_t b0, uint32_t b1) {
    asm volatile(
        "mma.sync.aligned.m16n8k16.row.col.f32.bf16.bf16.f32 "
        "{%0,%1,%2,%3}, {%4,%5,%6,%7}, {%8,%9}, {%0,%1,%2,%3};"
        : "+f"(d[0]), "+f"(d[1]), "+f"(d[2]), "+f"(d[3])
        : "r"(a[0]), "r"(a[1]), "r"(a[2]), "r"(a[3]), "r"(b0), "r"(b1));
}
__device__ __forceinline__ void split2(float v, __nv_bfloat16& h, __nv_bfloat16& l) {
    h = __float2bfloat16(v);
    l = __float2bfloat16(v - __bfloat162float(h));
}
__device__ __forceinline__ void cp16(uint32_t s, const void* g) {
    asm volatile("cp.async.cg.shared.global [%0], [%1], 16;" :: "r"(s), "l"(g));
}
#define CP_COMMIT() asm volatile("cp.async.commit_group;" ::: "memory")
#define CP_WAIT0()  asm volatile("cp.async.wait_group 0;" ::: "memory")
#define CP_WAIT1()  asm volatile("cp.async.wait_group 1;" ::: "memory")

#define SSTR 40                     // smem row stride (bf16): 80 B, ldsm conflict-free
#define TILEB (128 * SSTR * 2)      // 10240 B per 128x32 tile
#define TILEB64 (64 * SSTR * 2)     // 5120 B per 64x32 tile

// ================= bf16 hi/lo split (elementwise) ===============================
__global__ __launch_bounds__(256) void split_bf16(
    const float4* __restrict__ X, uint32_t* __restrict__ Hi,
    uint32_t* __restrict__ Lo, int n4)
{
    int i = blockIdx.x * 256 + threadIdx.x;
    if (i >= n4) return;
    float4 v = X[i];
    __nv_bfloat16 h0, h1, h2, h3, l0, l1, l2, l3;
    split2(v.x, h0, l0); split2(v.y, h1, l1);
    split2(v.z, h2, l2); split2(v.w, h3, l3);
    __nv_bfloat162 hA = {h0, h1}, hB = {h2, h3}, lA = {l0, l1}, lB = {l2, l3};
    Hi[2 * i] = *(uint32_t*)&hA; Hi[2 * i + 1] = *(uint32_t*)&hB;
    Lo[2 * i] = *(uint32_t*)&lA; Lo[2 * i + 1] = *(uint32_t*)&lB;
}

// ======== shared compute: 3-product fragment pass over one staged buffer ========
template <int NI>
__device__ __forceinline__ void mma_pass(
    uint32_t bAh, uint32_t bAl, uint32_t bBh, uint32_t bBl,
    int wm, int wn, int lane, float acc[2][NI][4])
{
#pragma unroll
    for (int ks = 0; ks < 2; ks++) {
        const int kb = ks * 16;
        uint32_t ah[2][4], al[2][4], bf[NI / 2][4];
        const uint32_t aoff = (((lane & 15)) * SSTR + kb + ((lane >> 4) * 8)) * 2;
#pragma unroll
        for (int mi = 0; mi < 2; mi++) {
            uint32_t ab = ((wm + mi * 16) * SSTR) * 2 + aoff;
            LDSM_X4(ah[mi][0], ah[mi][1], ah[mi][2], ah[mi][3], bAh + ab);
            LDSM_X4(al[mi][0], al[mi][1], al[mi][2], al[mi][3], bAl + ab);
        }
        const uint32_t boff =
            (((lane & 7) + (((lane >> 4) & 1) * 8)) * SSTR + kb + (((lane >> 3) & 1) * 8)) * 2;
#pragma unroll
        for (int ng = 0; ng < NI / 2; ng++) {
            uint32_t bb = ((wn + ng * 16) * SSTR) * 2 + boff;
            LDSM_X4(bf[ng][0], bf[ng][1], bf[ng][2], bf[ng][3], bBh + bb);
        }
#pragma unroll
        for (int mi = 0; mi < 2; mi++)
#pragma unroll
            for (int ng = 0; ng < NI / 2; ng++) {
                mma_bf16(acc[mi][2 * ng + 0], ah[mi], bf[ng][0], bf[ng][1]);
                mma_bf16(acc[mi][2 * ng + 1], ah[mi], bf[ng][2], bf[ng][3]);
                mma_bf16(acc[mi][2 * ng + 0], al[mi], bf[ng][0], bf[ng][1]);
                mma_bf16(acc[mi][2 * ng + 1], al[mi], bf[ng][2], bf[ng][3]);
            }
#pragma unroll
        for (int ng = 0; ng < NI / 2; ng++) {
            uint32_t bb = ((wn + ng * 16) * SSTR) * 2 + boff;
            LDSM_X4(bf[ng][0], bf[ng][1], bf[ng][2], bf[ng][3], bBl + bb);
        }
#pragma unroll
        for (int mi = 0; mi < 2; mi++)
#pragma unroll
            for (int ng = 0; ng < NI / 2; ng++) {
                mma_bf16(acc[mi][2 * ng + 0], ah[mi], bf[ng][0], bf[ng][1]);
                mma_bf16(acc[mi][2 * ng + 1], ah[mi], bf[ng][2], bf[ng][3]);
            }
    }
}

// ================= HMMA NT GEMM (4-tile staging, cp.async double-buffer) ========
extern __shared__ __align__(16) char dsm[];

__global__ __launch_bounds__(256, 2) void mma_gemm(
    const __nv_bfloat16* __restrict__ Ah, const __nv_bfloat16* __restrict__ Al,
    const __nv_bfloat16* __restrict__ Bh, const __nv_bfloat16* __restrict__ Bl,
    const float* __restrict__ bias, float* __restrict__ C, int Nd, int Kc)
{
    const int tid = threadIdx.x;
    const int lane = tid & 31, wid = tid >> 5;
    const int wm = (wid & 3) * 32;
    const int wn = (wid >> 2) * 64;
    const int m0 = blockIdx.y * 128, n0 = blockIdx.x * 128;

    const uint32_t base = smem_u32(dsm);
    const int r0 = tid >> 2, c0 = (tid & 3) * 8;
    const int r1 = (tid + 256) >> 2, c1 = ((tid + 256) & 3) * 8;
    const uint32_t s0 = (r0 * SSTR + c0) * 2, s1 = (r1 * SSTR + c1) * 2;

    const int kt = Kc / 32;

    float acc[2][8][4];
#pragma unroll
    for (int mi = 0; mi < 2; mi++)
#pragma unroll
        for (int ni = 0; ni < 8; ni++)
#pragma unroll
            for (int j = 0; j < 4; j++) acc[mi][ni][j] = 0.f;

    auto issue = [&](int k0, int buf) {
        uint32_t bb = base + buf * 4 * TILEB;
        cp16(bb + 0 * TILEB + s0, Ah + (size_t)(m0 + r0) * Kc + k0 + c0);
        cp16(bb + 0 * TILEB + s1, Ah + (size_t)(m0 + r1) * Kc + k0 + c1);
        cp16(bb + 1 * TILEB + s0, Al + (size_t)(m0 + r0) * Kc + k0 + c0);
        cp16(bb + 1 * TILEB + s1, Al + (size_t)(m0 + r1) * Kc + k0 + c1);
        cp16(bb + 2 * TILEB + s0, Bh + (size_t)(n0 + r0) * Kc + k0 + c0);
        cp16(bb + 2 * TILEB + s1, Bh + (size_t)(n0 + r1) * Kc + k0 + c1);
        cp16(bb + 3 * TILEB + s0, Bl + (size_t)(n0 + r0) * Kc + k0 + c0);
        cp16(bb + 3 * TILEB + s1, Bl + (size_t)(n0 + r1) * Kc + k0 + c1);
        CP_COMMIT();
    };

    issue(0, 0);
    for (int it = 0; it < kt; it++) {
        if (it + 1 < kt) { issue((it + 1) * 32, (it + 1) & 1); CP_WAIT1(); }
        else CP_WAIT0();
        __syncthreads();
        uint32_t bb = base + (it & 1) * 4 * TILEB;
        mma_pass<8>(bb, bb + TILEB, bb + 2 * TILEB, bb + 3 * TILEB,
                    wm, wn, lane, acc);
        __syncthreads();
    }

#pragma unroll
    for (int mi = 0; mi < 2; mi++)
#pragma unroll
        for (int ni = 0; ni < 8; ni++) {
            int row = m0 + wm + mi * 16 + (lane >> 2);
            int col = n0 + wn + ni * 8 + (lane & 3) * 2;
            float b0 = bias[col], b1 = bias[col + 1];
            float2 o0 = {acc[mi][ni][0] + b0, acc[mi][ni][1] + b1};
            float2 o1 = {acc[mi][ni][2] + b0, acc[mi][ni][3] + b1};
            *(float2*)&C[(size_t)row * Nd + col] = o0;
            *(float2*)&C[(size_t)(row + 8) * Nd + col] = o1;
        }
}

// ================= HMMA scores ==================================================
__global__ __launch_bounds__(256, 2) void mma_scores(
    const __nv_bfloat16* __restrict__ Qh, const __nv_bfloat16* __restrict__ Ql,
    const __nv_bfloat16* __restrict__ Kh, const __nv_bfloat16* __restrict__ Kl,
    const float* __restrict__ RH, const float* __restrict__ RW,
    float* __restrict__ P)
{
    const int tid = threadIdx.x;
    const int lane = tid & 31, wid = tid >> 5;
    const int wm = (wid & 3) * 32;
    const int wn = (wid >> 2) * 64;
    const int bn = blockIdx.z;
    const int m0 = blockIdx.y * 128, n0 = blockIdx.x * 128;
    const size_t hb = (size_t)bn * LSEQ * HD;
    const __nv_bfloat16* Qhp = Qh + hb; const __nv_bfloat16* Qlp = Ql + hb;
    const __nv_bfloat16* Khp = Kh + hb; const __nv_bfloat16* Klp = Kl + hb;

    const uint32_t base = smem_u32(dsm);
    const int r0 = tid >> 2, c0 = (tid & 3) * 8;
    const int r1 = (tid + 256) >> 2, c1 = ((tid + 256) & 3) * 8;
    const uint32_t s0 = (r0 * SSTR + c0) * 2, s1 = (r1 * SSTR + c1) * 2;

    float acc[2][8][4];
#pragma unroll
    for (int mi = 0; mi < 2; mi++)
#pragma unroll
        for (int ni = 0; ni < 8; ni++)
#pragma unroll
            for (int j = 0; j < 4; j++) acc[mi][ni][j] = 0.f;

    auto issue = [&](int k0, int buf) {
        uint32_t bb = base + buf * 4 * TILEB;
        cp16(bb + 0 * TILEB + s0, Qhp + (size_t)(m0 + r0) * HD + k0 + c0);
        cp16(bb + 0 * TILEB + s1, Qhp + (size_t)(m0 + r1) * HD + k0 + c1);
        cp16(bb + 1 * TILEB + s0, Qlp + (size_t)(m0 + r0) * HD + k0 + c0);
        cp16(bb + 1 * TILEB + s1, Qlp + (size_t)(m0 + r1) * HD + k0 + c1);
        cp16(bb + 2 * TILEB + s0, Khp + (size_t)(n0 + r0) * HD + k0 + c0);
        cp16(bb + 2 * TILEB + s1, Khp + (size_t)(n0 + r1) * HD + k0 + c1);
        cp16(bb + 3 * TILEB + s0, Klp + (size_t)(n0 + r0) * HD + k0 + c0);
        cp16(bb + 3 * TILEB + s1, Klp + (size_t)(n0 + r1) * HD + k0 + c1);
        CP_COMMIT();
    };

    issue(0, 0);
    for (int it = 0; it < 2; it++) {
        if (it == 0) { issue(32, 1); CP_WAIT1(); }
        else CP_WAIT0();
        __syncthreads();
        uint32_t bb = base + (it & 1) * 4 * TILEB;
        mma_pass<8>(bb, bb + TILEB, bb + 2 * TILEB, bb + 3 * TILEB,
                    wm, wn, lane, acc);
        __syncthreads();
    }

    float* Pb = P + (size_t)bn * LSEQ * LSEQ;
#pragma unroll
    for (int mi = 0; mi < 2; mi++)
#pragma unroll
        for (int ni = 0; ni < 8; ni++) {
            int row = m0 + wm + mi * 16 + (lane >> 2);
            int col = n0 + wn + ni * 8 + (lane & 3) * 2;
            const float* rh0 = RH + ((size_t)bn * LSEQ + row) * 32;
            const float* rw0 = RW + ((size_t)bn * LSEQ + row) * 32;
            const float* rh1 = rh0 + 8 * 32;
            const float* rw1 = rw0 + 8 * 32;
            float bh0 = rh0[col >> 5], bh1 = rh1[col >> 5];
            int cw = col & 31;
            float2 o0 = {fmaf(acc[mi][ni][0], 0.125f, bh0 + rw0[cw]),
                         fmaf(acc[mi][ni][1], 0.125f, bh0 + rw0[cw + 1])};
            float2 o1 = {fmaf(acc[mi][ni][2], 0.125f, bh1 + rw1[cw]),
                         fmaf(acc[mi][ni][3], 0.125f, bh1 + rw1[cw + 1])};
            *(float2*)&Pb[(size_t)row * LSEQ + col] = o0;
            *(float2*)&Pb[(size_t)(row + 8) * LSEQ + col] = o1;
        }
}

// ================= HMMA AV ======================================================
#define AVBUF (2 * TILEB + 2 * TILEB64)   // Ph, Pl (128x32) + Vh, Vl (64x32)

__global__ __launch_bounds__(256, 2) void mma_av(
    const __nv_bfloat16* __restrict__ Ph, const __nv_bfloat16* __restrict__ Pl,
    const __nv_bfloat16* __restrict__ Vth, const __nv_bfloat16* __restrict__ Vtl,
    __nv_bfloat16* __restrict__ OutH, __nv_bfloat16* __restrict__ OutL)
{
    const int tid = threadIdx.x;
    const int lane = tid & 31, wid = tid >> 5;
    const int wm = (wid & 3) * 32;
    const int wn = (wid >> 2) * 32;
    const int bn = blockIdx.z, b = bn / NH, n = bn % NH;
    const int m0 = blockIdx.y * 128;
    const __nv_bfloat16* Php = Ph + (size_t)bn * LSEQ * LSEQ;
    const __nv_bfloat16* Plp = Pl + (size_t)bn * LSEQ * LSEQ;
    const __nv_bfloat16* Vhp = Vth + (size_t)bn * HD * LSEQ;
    const __nv_bfloat16* Vlp = Vtl + (size_t)bn * HD * LSEQ;

    const uint32_t base = smem_u32(dsm);
    const int r0 = tid >> 2, c0 = (tid & 3) * 8;
    const int r1 = (tid + 256) >> 2, c1 = ((tid + 256) & 3) * 8;
    const uint32_t s0 = (r0 * SSTR + c0) * 2, s1 = (r1 * SSTR + c1) * 2;

    float acc[2][4][4];
#pragma unroll
    for (int mi = 0; mi < 2; mi++)
#pragma unroll
        for (int ni = 0; ni < 4; ni++)
#pragma unroll
            for (int j = 0; j < 4; j++) acc[mi][ni][j] = 0.f;

    auto issue = [&](int k0, int buf) {
        uint32_t bb = base + buf * AVBUF;
        cp16(bb + 0 * TILEB + s0, Php + (size_t)(m0 + r0) * LSEQ + k0 + c0);
        cp16(bb + 0 * TILEB + s1, Php + (size_t)(m0 + r1) * LSEQ + k0 + c1);
        cp16(bb + 1 * TILEB + s0, Plp + (size_t)(m0 + r0) * LSEQ + k0 + c0);
        cp16(bb + 1 * TILEB + s1, Plp + (size_t)(m0 + r1) * LSEQ + k0 + c1);
        cp16(bb + 2 * TILEB + s0, Vhp + (size_t)r0 * LSEQ + k0 + c0);
        cp16(bb + 2 * TILEB + TILEB64 + s0, Vlp + (size_t)r0 * LSEQ + k0 + c0);
        CP_COMMIT();
    };

    const int kt = LSEQ / 32;
    issue(0, 0);
    for (int it = 0; it < kt; it++) {
        if (it + 1 < kt) { issue((it + 1) * 32, (it + 1) & 1); CP_WAIT1(); }
        else CP_WAIT0();
        __syncthreads();
        uint32_t bb = base + (it & 1) * AVBUF;
        mma_pass<4>(bb, bb + TILEB, bb + 2 * TILEB, bb + 2 * TILEB + TILEB64,
                    wm, wn, lane, acc);
        __syncthreads();
    }

#pragma unroll
    for (int mi = 0; mi < 2; mi++)
#pragma unroll
        for (int ni = 0; ni < 4; ni++) {
            int row = m0 + wm + mi * 16 + (lane >> 2);
            int col = wn + ni * 8 + (lane & 3) * 2;
#pragma unroll
            for (int half = 0; half < 2; half++) {
                int r = row + half * 8;
                float v0 = acc[mi][ni][2 * half], v1 = acc[mi][ni][2 * half + 1];
                __nv_bfloat16 h0, h1, l0, l1;
                split2(v0, h0, l0); split2(v1, h1, l1);
                __nv_bfloat162 hp = {h0, h1}, lp = {l0, l1};
                size_t e = ((size_t)(b * LSEQ + r)) * DIM + n * HD + col;
                *(uint32_t*)&OutH[e] = *(uint32_t*)&hp;
                *(uint32_t*)&OutL[e] = *(uint32_t*)&lp;
            }
        }
}

// ================= split qkv + 2D axial RoPE ====================================
__global__ __launch_bounds__(256) void rope_split_kernel(
    const float* __restrict__ qkv, float* __restrict__ qf,
    __nv_bfloat16* __restrict__ qh, __nv_bfloat16* __restrict__ ql,
    __nv_bfloat16* __restrict__ kh, __nv_bfloat16* __restrict__ kl)
{
    int idx = blockIdx.x * blockDim.x + threadIdx.x;
    const int TOT = NHEADS * LSEQ * (HD / 2);
    if (idx >= TOT) return;
    int j = idx & 31;
    int l = (idx >> 5) & (LSEQ - 1);
    int n = (idx >> 15) % NH;
    int b = idx / (32 * LSEQ * NH);

    size_t in_base = ((size_t)(b * LSEQ + l)) * NQKV + n * HD + 2 * j;
    size_t out_base = ((size_t)((b * NH + n) * LSEQ + l)) * HD + 2 * j;

    int i = j & 15;
    float pos = (j < 16) ? (float)(l & 31) : (float)(l >> 5);
    float f = exp2f(-(float)i * (13.287712379549449f / 16.0f));
    float sn, cs;
    sincosf(pos * f, &sn, &cs);

    float2 qa = *(const float2*)&qkv[in_base];
    float2 ka = *(const float2*)&qkv[in_base + DIM];
    float2 qo, ko;
    qo.x = qa.x * cs - qa.y * sn; qo.y = qa.x * sn + qa.y * cs;
    ko.x = ka.x * cs - ka.y * sn; ko.y = ka.x * sn + ka.y * cs;

    *(float2*)&qf[out_base] = qo;
    __nv_bfloat16 h0, h1, l0, l1;
    split2(qo.x, h0, l0); split2(qo.y, h1, l1);
    __nv_bfloat162 qhp = {h0, h1}, qlp = {l0, l1};
    *(uint32_t*)&qh[out_base] = *(uint32_t*)&qhp;
    *(uint32_t*)&ql[out_base] = *(uint32_t*)&qlp;
    split2(ko.x, h0, l0); split2(ko.y, h1, l1);
    __nv_bfloat162 khp = {h0, h1}, klp = {l0, l1};
    *(uint32_t*)&kh[out_base] = *(uint32_t*)&khp;
    *(uint32_t*)&kl[out_base] = *(uint32_t*)&klp;
}

// ================= V transpose -> bf16 hi/lo ====================================
__global__ __launch_bounds__(256) void vtrans_kernel(
    const float* __restrict__ qkv, __nv_bfloat16* __restrict__ Vth,
    __nv_bfloat16* __restrict__ Vtl)
{
    __shared__ float s[32][33];
    int bn = blockIdx.z, b = bn / NH, n = bn % NH;
    int l0 = blockIdx.x * 32, d0 = blockIdx.y * 32;
    int tx = threadIdx.x, ty = threadIdx.y;
#pragma unroll
    for (int i = 0; i < 32; i += 8)
        s[ty + i][tx] = qkv[(size_t)(b * LSEQ + l0 + ty + i) * NQKV + 2 * DIM + n * HD + d0 + tx];
    __syncthreads();
#pragma unroll
    for (int i = 0; i < 32; i += 8) {
        float v = s[tx][ty + i];
        __nv_bfloat16 h, l;
        split2(v, h, l);
        size_t e = (size_t)(bn * HD + d0 + ty + i) * LSEQ + l0 + tx;
        Vth[e] = h;
        Vtl[e] = l;
    }
}

// ================= rel-pos bias precompute ======================================
__global__ __launch_bounds__(256) void relbias_kernel(
    const float* __restrict__ Q, const float* __restrict__ rph,
    const float* __restrict__ rpw, float* __restrict__ RH, float* __restrict__ RW)
{
    __shared__ float qs[32][68];
    __shared__ float ts[32][68];
    const int bn = blockIdx.x;
    const int coord = blockIdx.y;
    const int mode = blockIdx.z;
    const int tid = threadIdx.x;

    {
        int r = tid >> 3;
        int c = (tid & 7) * 8;
        int l = (mode == 0) ? (coord * 32 + r) : (r * 32 + coord);
        const float* qrow = Q + ((size_t)bn * LSEQ + l) * HD;
        *(float4*)&qs[r][c]     = *(const float4*)&qrow[c];
        *(float4*)&qs[r][c + 4] = *(const float4*)&qrow[c + 4];
        const float* trow = ((mode == 0) ? rph : rpw) + (size_t)(coord - r + 31) * HD;
        *(float4*)&ts[r][c]     = *(const float4*)&trow[c];
        *(float4*)&ts[r][c + 4] = *(const float4*)&trow[c + 4];
    }
    __syncthreads();

    const int qq = tid >> 3;
    const int k0 = tid & 7;
    float acc[4] = {0.f, 0.f, 0.f, 0.f};
#pragma unroll
    for (int d = 0; d < HD; d += 4) {
        float4 q4 = *(const float4*)&qs[qq][d];
#pragma unroll
        for (int j = 0; j < 4; j++) {
            float4 t4 = *(const float4*)&ts[k0 + 8 * j][d];
            acc[j] = fmaf(q4.x, t4.x, fmaf(q4.y, t4.y,
                     fmaf(q4.z, t4.z, fmaf(q4.w, t4.w, acc[j]))));
        }
    }
    int lo = (mode == 0) ? (coord * 32 + qq) : (qq * 32 + coord);
    float* dst = ((mode == 0) ? RH : RW) + ((size_t)bn * LSEQ + lo) * 32;
#pragma unroll
    for (int j = 0; j < 4; j++) dst[k0 + 8 * j] = acc[j];
}

// ================= row softmax -> bf16 hi/lo probabilities ======================
__device__ __forceinline__ float fexp_neg(float x) {
    float t = fmaxf(x * 1.4426950408889634f, -126.0f);
    float fl = floorf(t);
    float f = t - fl;
    float p = 1.5403530e-4f;
    p = fmaf(p, f, 1.3333558e-3f);
    p = fmaf(p, f, 9.6181291e-3f);
    p = fmaf(p, f, 5.5504109e-2f);
    p = fmaf(p, f, 2.4022651e-1f);
    p = fmaf(p, f, 6.9314718e-1f);
    p = fmaf(p, f, 1.0f);
    int i = (int)fl;
    return p * __int_as_float((i + 127) << 23);
}

__global__ __launch_bounds__(256) void softmax_rows(
    const float* __restrict__ P, __nv_bfloat16* __restrict__ Ph,
    __nv_bfloat16* __restrict__ Pl)
{
    __shared__ float rmax[8], rsum[8];
    const float* p = P + (size_t)blockIdx.x * LSEQ;
    int tid = threadIdx.x;
    float4 v = ((const float4*)p)[tid];
    float m = fmaxf(fmaxf(v.x, v.y), fmaxf(v.z, v.w));
#pragma unroll
    for (int o = 16; o; o >>= 1) m = fmaxf(m, __shfl_xor_sync(0xffffffffu, m, o));
    if ((tid & 31) == 0) rmax[tid >> 5] = m;
    __syncthreads();
    m = rmax[0];
#pragma unroll
    for (int i = 1; i < 8; i++) m = fmaxf(m, rmax[i]);

    v.x = fexp_neg(v.x - m); v.y = fexp_neg(v.y - m);
    v.z = fexp_neg(v.z - m); v.w = fexp_neg(v.w - m);
    float s = (v.x + v.y) + (v.z + v.w);
#pragma unroll
    for (int o = 16; o; o >>= 1) s += __shfl_xor_sync(0xffffffffu, s, o);
    if ((tid & 31) == 0) rsum[tid >> 5] = s;
    __syncthreads();
    s = ((rsum[0] + rsum[1]) + (rsum[2] + rsum[3])) +
        ((rsum[4] + rsum[5]) + (rsum[6] + rsum[7]));
    float r = __fdividef(1.0f, s);
    v.x *= r; v.y *= r; v.z *= r; v.w *= r;

    __nv_bfloat16 h0, h1, h2, h3, l0, l1, l2, l3;
    split2(v.x, h0, l0); split2(v.y, h1, l1);
    split2(v.z, h2, l2); split2(v.w, h3, l3);
    __nv_bfloat162 hA = {h0, h1}, hB = {h2, h3}, lA = {l0, l1}, lB = {l2, l3};
    size_t e = (size_t)blockIdx.x * LSEQ + tid * 4;
    *(uint32_t*)&Ph[e]     = *(uint32_t*)&hA;
    *(uint32_t*)&Ph[e + 2] = *(uint32_t*)&hB;
    *(uint32_t*)&Pl[e]     = *(uint32_t*)&lA;
    *(uint32_t*)&Pl[e + 2] = *(uint32_t*)&lB;
}

// ================= launch ========================================================
extern "C" void kernel_launch(void* const* d_in, const int* in_sizes, int n_in,
                              void* d_out, int out_size)
{
    const float* x      = (const float*)d_in[0];
    const float* qkv_w  = (const float*)d_in[1];
    const float* qkv_b  = (const float*)d_in[2];
    const float* proj_w = (const float*)d_in[3];
    const float* proj_b = (const float*)d_in[4];
    const float* rph    = (const float*)d_in[5];
    const float* rpw    = (const float*)d_in[6];
    float* out = (float*)d_out;

    float *p_qkv, *p_qf, *p_P, *p_rh, *p_rw;
    __nv_bfloat16 *p_xh, *p_xl, *p_wqh, *p_wql, *p_ath, *p_atl, *p_wph, *p_wpl;
    __nv_bfloat16 *p_qh, *p_ql, *p_kh, *p_kl, *p_vth, *p_vtl, *p_Ph, *p_Pl;
    cudaGetSymbolAddress((void**)&p_qkv, g_qkv);
    cudaGetSymbolAddress((void**)&p_qf,  g_qf);
    cudaGetSymbolAddress((void**)&p_P,   g_P);
    cudaGetSymbolAddress((void**)&p_rh,  g_rh);
    cudaGetSymbolAddress((void**)&p_rw,  g_rw);
    cudaGetSymbolAddress((void**)&p_xh,  g_xh);
    cudaGetSymbolAddress((void**)&p_xl,  g_xl);
    cudaGetSymbolAddress((void**)&p_wqh, g_wqh);
    cudaGetSymbolAddress((void**)&p_wql, g_wql);
    cudaGetSymbolAddress((void**)&p_ath, g_ath);
    cudaGetSymbolAddress((void**)&p_atl, g_atl);
    cudaGetSymbolAddress((void**)&p_wph, g_wph);
    cudaGetSymbolAddress((void**)&p_wpl, g_wpl);
    cudaGetSymbolAddress((void**)&p_qh,  g_qh);
    cudaGetSymbolAddress((void**)&p_ql,  g_ql);
    cudaGetSymbolAddress((void**)&p_kh,  g_kh);
    cudaGetSymbolAddress((void**)&p_kl,  g_kl);
    cudaGetSymbolAddress((void**)&p_vth, g_vth);
    cudaGetSymbolAddress((void**)&p_vtl, g_vtl);
    cudaGetSymbolAddress((void**)&p_Ph,  g_Ph);
    cudaGetSymbolAddress((void**)&p_Pl,  g_Pl);

    const int GEMM_SMEM = 2 * 4 * TILEB;   // 81920
    const int AV_SMEM   = 2 * AVBUF;       // 61440
    cudaFuncSetAttribute(mma_gemm, cudaFuncAttributeMaxDynamicSharedMemorySize, GEMM_SMEM);
    cudaFuncSetAttribute(mma_scores, cudaFuncAttributeMaxDynamicSharedMemorySize, GEMM_SMEM);
    cudaFuncSetAttribute(mma_av, cudaFuncAttributeMaxDynamicSharedMemorySize, AV_SMEM);

    // 0) bf16 splits of x and weights
    {
        int n4 = MROWS * DIM / 4;
        split_bf16<<<(n4 + 255) / 256, 256>>>((const float4*)x, (uint32_t*)p_xh,
                                              (uint32_t*)p_xl, n4);
        n4 = NQKV * DIM / 4;
        split_bf16<<<(n4 + 255) / 256, 256>>>((const float4*)qkv_w, (uint32_t*)p_wqh,
                                              (uint32_t*)p_wql, n4);
        n4 = DIM * DIM / 4;
        split_bf16<<<(n4 + 255) / 256, 256>>>((const float4*)proj_w, (uint32_t*)p_wph,
                                              (uint32_t*)p_wpl, n4);
    }

    // 1) QKV GEMM (HMMA)
    mma_gemm<<<dim3(NQKV / 128, MROWS / 128), 256, GEMM_SMEM>>>(
        p_xh, p_xl, p_wqh, p_wql, qkv_b, p_qkv, NQKV, DIM);

    // 2) split + rope
    {
        const int TOT = NHEADS * LSEQ * (HD / 2);
        rope_split_kernel<<<(TOT + 255) / 256, 256>>>(p_qkv, p_qf, p_qh, p_ql,
                                                      p_kh, p_kl);
    }

    // 3) V transpose
    vtrans_kernel<<<dim3(LSEQ / 32, HD / 32, NHEADS), dim3(32, 8)>>>(
        p_qkv, p_vth, p_vtl);

    // 4) rel-pos bias precompute
    relbias_kernel<<<dim3(NHEADS, 32, 2), 256>>>(p_qf, rph, rpw, p_rh, p_rw);

    // 5) scores GEMM (HMMA)
    mma_scores<<<dim3(LSEQ / 128, LSEQ / 128, NHEADS), 256, GEMM_SMEM>>>(
        p_qh, p_ql, p_kh, p_kl, p_rh, p_rw, p_P);

    // 6) row softmax -> bf16 hi/lo probs
    softmax_rows<<<NHEADS * LSEQ, 256>>>(p_P, p_Ph, p_Pl);

    // 7) AV GEMM (HMMA)
    mma_av<<<dim3(1, LSEQ / 128, NHEADS), 256, AV_SMEM>>>(p_Ph, p_Pl, p_vth, p_vtl,
                                                          p_ath, p_atl);

    // 8) output projection (HMMA)
    mma_gemm<<<dim3(DIM / 128, MROWS / 128), 256, GEMM_SMEM>>>(
        p_ath, p_atl, p_wph, p_wpl, proj_b, out, DIM, DIM);
}